// round 13
// baseline (speedup 1.0000x reference)
#include <cuda_runtime.h>
#include <cstdint>

#define NQ   14
#define NL   4
#define DIM  16384
#define NT   512
#define SEQL 8

typedef unsigned long long ull;

__device__ __forceinline__ ull f2mul(ull a, ull b) {
    ull d; asm("mul.rn.f32x2 %0, %1, %2;" : "=l"(d) : "l"(a), "l"(b)); return d;
}
__device__ __forceinline__ ull f2fma(ull a, ull b, ull c) {
    ull d; asm("fma.rn.f32x2 %0, %1, %2, %3;" : "=l"(d) : "l"(a), "l"(b), "l"(c)); return d;
}
__device__ __forceinline__ ull f2add(ull a, ull b) {
    ull d; asm("add.rn.f32x2 %0, %1, %2;" : "=l"(d) : "l"(a), "l"(b)); return d;
}
__device__ __forceinline__ ull pk(float lo, float hi) {
    ull r; asm("mov.b64 %0, {%1, %2};" : "=l"(r) : "f"(lo), "f"(hi)); return r;
}
__device__ __forceinline__ void upk(ull v, float& lo, float& hi) {
    asm("mov.b64 {%0, %1}, %2;" : "=f"(lo), "=f"(hi) : "l"(v));
}
__device__ __forceinline__ ull lswap(ull v) {
    float lo, hi; upk(v, lo, hi); return pk(hi, lo);
}

__device__ __forceinline__ int swz4(int j) { return j ^ ((j >> 4) & 15); }

template<int NB, int J>
__device__ __forceinline__ void gateP(ull* re, ull* im, const ull* g) {
    ull Ax = g[0], Ay = g[1], nAy = g[2], Az = g[3], Aw = g[4], nAw = g[5];
    ull Bx = g[6], By = g[7], nBy = g[8], Bz = g[9], Bw = g[10], nBw = g[11];
#pragma unroll
    for (int k = 0; k < (1 << NB); ++k)
        if (!(k & (1 << J))) {
            const int m = k | (1 << J);
            ull p0r = re[k], p0i = im[k], p1r = re[m], p1i = im[m];
            ull n0r = f2fma(nAw, p1i, f2fma(Az, p1r, f2fma(nAy, p0i, f2mul(Ax, p0r))));
            ull n0i = f2fma(Aw,  p1r, f2fma(Az, p1i, f2fma(Ay,  p0r, f2mul(Ax, p0i))));
            ull n1r = f2fma(nBw, p1i, f2fma(Bz, p1r, f2fma(nBy, p0i, f2mul(Bx, p0r))));
            ull n1i = f2fma(Bw,  p1r, f2fma(Bz, p1i, f2fma(By,  p0r, f2mul(Bx, p0i))));
            re[k] = n0r; im[k] = n0i; re[m] = n1r; im[m] = n1i;
        }
}

template<int NB, int JC, int JT>
__device__ __forceinline__ void cnotP(ull* re, ull* im) {
#pragma unroll
    for (int k = 0; k < (1 << NB); ++k)
        if ((k & (1 << JC)) && !(k & (1 << JT))) {
            const int m = k | (1 << JT);
            ull t = re[k]; re[k] = re[m]; re[m] = t;
            t = im[k]; im[k] = im[m]; im[m] = t;
        }
}

template<int NB, int JT>
__device__ __forceinline__ void cswapHalf(ull* re, ull* im, bool pred) {
    if (pred) {
#pragma unroll
        for (int k = 0; k < (1 << NB); ++k)
            if (!(k & (1 << JT))) {
                const int m = k | (1 << JT);
                ull t = re[k]; re[k] = re[m]; re[m] = t;
                t = im[k]; im[k] = im[m]; im[m] = t;
            }
    }
}

// interleaved state: float4 {re_lo, re_hi, im_lo, im_hi} per pair index
template<int J0,int J1,int J2,int J3>
__device__ __forceinline__ void load16(ull* re, ull* im, const float4* st, int pjb) {
#pragma unroll
    for (int k = 0; k < 16; ++k) {
        int joff = ((k&1)?(1<<J0):0) | ((k&2)?(1<<J1):0)
                 | ((k&4)?(1<<J2):0) | ((k&8)?(1<<J3):0);
        int a = pjb ^ (joff ^ ((joff >> 4) & 15));
        float4 v = st[a];
        re[k] = pk(v.x, v.y); im[k] = pk(v.z, v.w);
    }
}
template<int J0,int J1,int J2,int J3>
__device__ __forceinline__ void store16(const ull* re, const ull* im, float4* st, int pjb) {
#pragma unroll
    for (int k = 0; k < 16; ++k) {
        int joff = ((k&1)?(1<<J0):0) | ((k&2)?(1<<J1):0)
                 | ((k&4)?(1<<J2):0) | ((k&8)?(1<<J3):0);
        int a = pjb ^ (joff ^ ((joff >> 4) & 15));
        float rl, rh, il, ih;
        upk(re[k], rl, rh); upk(im[k], il, ih);
        st[a] = make_float4(rl, rh, il, ih);
    }
}

__device__ __forceinline__ float2 cmulf(float2 a, float2 b) {
    return make_float2(a.x*b.x - a.y*b.y, a.x*b.y + a.y*b.x);
}

__device__ __forceinline__ void gateLaneAll(ull* re, ull* im, const ull* g13) {
    ull C1 = g13[0], C2 = g13[1], nC2 = g13[2],
        C3 = g13[3], C4 = g13[4], nC4 = g13[5];
#pragma unroll
    for (int k = 0; k < 16; ++k) {
        ull qr = lswap(re[k]), qi = lswap(im[k]);
        ull nr = f2fma(C4,  qi, f2fma(C3, qr, f2fma(C2,  im[k], f2mul(C1, re[k]))));
        ull ni = f2fma(nC4, qr, f2fma(C3, qi, f2fma(nC2, re[k], f2mul(C1, im[k]))));
        re[k] = nr; im[k] = ni;
    }
}

__device__ __forceinline__ void carriedSwap(ull* re, ull* im) {
#pragma unroll
    for (int k1 = 0; k1 < 8; ++k1) {
        float alo, ahi, blo, bhi;
        upk(re[k1], alo, ahi); upk(re[k1|8], blo, bhi);
        re[k1] = pk(alo, bhi); re[k1|8] = pk(blo, ahi);
        upk(im[k1], alo, ahi); upk(im[k1|8], blo, bhi);
        im[k1] = pk(alo, bhi); im[k1|8] = pk(blo, ahi);
    }
}

__device__ __forceinline__ void gateShfl(ull* re, ull* im, const ull* gr) {
    ull Ax = gr[0], Ay = gr[1], nAy = gr[2], Az = gr[3], Aw = gr[4], nAw = gr[5];
#pragma unroll
    for (int k = 0; k < 16; ++k) {
        ull qr = __shfl_xor_sync(0xffffffffu, re[k], 1);
        ull qi = __shfl_xor_sync(0xffffffffu, im[k], 1);
        ull nr = f2fma(nAw, qi, f2fma(Az, qr, f2fma(nAy, im[k], f2mul(Ax, re[k]))));
        ull ni = f2fma(Aw,  qr, f2fma(Az, qi, f2fma(Ay,  re[k], f2mul(Ax, im[k]))));
        re[k] = nr; im[k] = ni;
    }
}

__device__ __forceinline__ void pass_a(float4* st, const float* gl, int tid, bool carry) {
    int pjb = swz4(tid);
    ull re[16], im[16];
    load16<9,10,11,12>(re, im, st, pjb);
    if (carry) carriedSwap(re, im);
    gateP<4,3>(re, im, (const ull*)(gl + 0*24));
    gateP<4,2>(re, im, (const ull*)(gl + 1*24));
    gateP<4,1>(re, im, (const ull*)(gl + 2*24));
    gateP<4,0>(re, im, (const ull*)(gl + 3*24));
    gateLaneAll(re, im, (const ull*)(gl + 13*24));
    cnotP<4,3,2>(re, im); cnotP<4,2,1>(re, im); cnotP<4,1,0>(re, im);
    store16<9,10,11,12>(re, im, st, pjb);
}
__device__ __forceinline__ void pass_b(float4* st, const float* gl, int tid) {
    int base = (tid & 31) | ((tid >> 5) << 9);
    int pjb = swz4(base);
    ull re[16], im[16];
    load16<5,6,7,8>(re, im, st, pjb);
    gateP<4,3>(re, im, (const ull*)(gl + 4*24));
    gateP<4,2>(re, im, (const ull*)(gl + 5*24));
    gateP<4,1>(re, im, (const ull*)(gl + 6*24));
    gateP<4,0>(re, im, (const ull*)(gl + 7*24));
    cswapHalf<4,3>(re, im, (tid >> 5) & 1);
    cnotP<4,3,2>(re, im); cnotP<4,2,1>(re, im); cnotP<4,1,0>(re, im);
    store16<5,6,7,8>(re, im, st, pjb);
}
__device__ __forceinline__ void pass_c(float4* st, const float* gl,
                                       const float* g8, int tid) {
    int pjb = swz4(tid << 4);
    ull re[16], im[16];
    load16<0,1,2,3>(re, im, st, pjb);
    gateShfl(re, im, (const ull*)(g8 + (tid & 3) * 12));
    gateP<4,3>(re, im, (const ull*)(gl + 9*24));
    gateP<4,2>(re, im, (const ull*)(gl + 10*24));
    gateP<4,1>(re, im, (const ull*)(gl + 11*24));
    gateP<4,0>(re, im, (const ull*)(gl + 12*24));
    cswapHalf<4,3>(re, im, tid & 1);
    cnotP<4,3,2>(re, im); cnotP<4,2,1>(re, im); cnotP<4,1,0>(re, im);
#pragma unroll
    for (int k = 1; k < 16; k += 2) { re[k] = lswap(re[k]); im[k] = lswap(im[k]); }
    store16<0,1,2,3>(re, im, st, pjb);
}

__global__ void __launch_bounds__(NT, 1)
vqc_kernel(const float* __restrict__ x,    const float* __restrict__ w_in,
           const float* __restrict__ b_in, const float* __restrict__ wts,
           const float* __restrict__ w_out,const float* __restrict__ b_out,
           float* __restrict__ out)
{
    extern __shared__ float smem[];
    float4* st   = (float4*)smem;           // 8192 float4 = 2*DIM floats
    float* gmat  = smem + 2 * DIM;          // 1008
    float* g8tab = gmat + 42 * 24;          // 144
    float* enc   = g8tab + 144;             // 28
    float* red   = enc + 28;                // 240
    float2* ftab = (float2*)red;            // init factor table (56 floats)

    const int b = blockIdx.x, tid = threadIdx.x;

    if (tid < NQ) {
        float acc = b_in[tid];
#pragma unroll
        for (int s2 = 0; s2 < SEQL; ++s2) acc += x[b*SEQL + s2] * w_in[tid*SEQL + s2];
        enc[2*tid]     = cospif(0.5f * acc);
        enc[2*tid + 1] = sinpif(0.5f * acc);
    }
    __syncthreads();

    if (tid < NQ * NL) {
        int i = tid % NQ, j = tid / NQ;
        const float* w = wts + (i*NL + j)*3;
        float cx = cosf(0.5f*w[0]), sx = sinf(0.5f*w[0]);
        float cy = cosf(0.5f*w[1]), sy = sinf(0.5f*w[1]);
        float cz = cosf(0.5f*w[2]), sz = sinf(0.5f*w[2]);
        if (j == 3) { cz = 1.f; sz = 0.f; }
        float2 m00 = make_float2( cy*cx,  sy*sx);
        float2 m01 = make_float2(-sy*cx, -cy*sx);
        float2 m10 = make_float2( sy*cx, -cy*sx);
        float2 m11 = make_float2( cy*cx, -sy*sx);
        float2 e0 = make_float2(cz, -sz), e1 = make_float2(cz, sz);
        float2 u00 = cmulf(e0, m00), u01 = cmulf(e0, m01);
        float2 u10 = cmulf(e1, m10), u11 = cmulf(e1, m11);
        if (j == 0) {
            float c = enc[2*i], s = enc[2*i+1];
            int t = 13 - i;
            ftab[t*2 + 0] = make_float2(u00.x*c + u01.x*s, u00.y*c + u01.y*s);
            ftab[t*2 + 1] = make_float2(u10.x*c + u11.x*s, u10.y*c + u11.y*s);
        } else if (i == 8) {
            float2 Ca[4] = { u00, u11, u10, u01 };
            float2 Cb[4] = { u01, u10, u11, u00 };
#pragma unroll
            for (int s4 = 0; s4 < 4; ++s4) {
                float* r = g8tab + ((j-1)*4 + s4)*12;
                r[0]=Ca[s4].x; r[1]=Ca[s4].x;  r[2]=Ca[s4].y; r[3]=Ca[s4].y;
                r[4]=-Ca[s4].y; r[5]=-Ca[s4].y; r[6]=Cb[s4].x; r[7]=Cb[s4].x;
                r[8]=Cb[s4].y; r[9]=Cb[s4].y;  r[10]=-Cb[s4].y; r[11]=-Cb[s4].y;
            }
        } else {
            float* g = gmat + ((j-1)*NQ + i)*24;
            if (i < 13) {
                float c[12] = { u00.x, u00.y, -u00.y, u01.x, u01.y, -u01.y,
                                u10.x, u10.y, -u10.y, u11.x, u11.y, -u11.y };
#pragma unroll
                for (int q = 0; q < 12; ++q) { g[2*q] = c[q]; g[2*q+1] = c[q]; }
            } else {
                g[0] = u00.x;  g[1] = u11.x;
                g[2] = -u00.y; g[3] = -u11.y;
                g[4] = u00.y;  g[5] = u11.y;
                g[6] = u01.x;  g[7] = u10.x;
                g[8] = -u01.y; g[9] = -u10.y;
                g[10] = u01.y; g[11] = u10.y;
            }
        }
    }
    __syncthreads();

    // --- layer 2 pass A fused with init: synthesize amps in registers.
    {
        const float* gl = gmat;
        int gx = tid ^ (tid >> 1);
        float2 P8 = ftab[2 + (gx & 1)];
#pragma unroll
        for (int t = 2; t <= 8; ++t)
            P8 = cmulf(P8, ftab[t*2 + ((gx >> (t-1)) & 1)]);
        float2 Bl0 = cmulf(P8, ftab[0 + (tid & 1)]);
        float2 Bl1 = cmulf(P8, ftab[0 + ((tid & 1) ^ 1)]);
        float2 G00 = cmulf(ftab[24], ftab[26]);
        float2 G01 = cmulf(ftab[24], ftab[27]);
        float2 G10 = cmulf(ftab[25], ftab[26]);
        float2 G11 = cmulf(ftab[25], ftab[27]);
        int t8 = (tid >> 8) & 1;
        ull re[16], im[16];
#pragma unroll
        for (int k = 0; k < 16; ++k) {
            const int k0 = k & 1, k1 = (k >> 1) & 1, k2 = (k >> 2) & 1, k3 = (k >> 3) & 1;
            float2 H3 = cmulf(cmulf(ftab[18 + (t8 ^ k0)], ftab[20 + (k0 ^ k1)]),
                              ftab[22 + (k1 ^ k2)]);
            const int a0 = k2 ^ k3, b0c = k3;
            float2 HL0 = cmulf(H3, a0 ? (b0c ? G11 : G10) : (b0c ? G01 : G00));
            float2 HL1 = cmulf(H3, (a0^1) ? ((b0c^1) ? G11 : G10) : ((b0c^1) ? G01 : G00));
            float2 lo = cmulf(Bl0, HL0);
            float2 hi = cmulf(Bl1, HL1);
            re[k] = pk(lo.x, hi.x);
            im[k] = pk(lo.y, hi.y);
        }
        gateP<4,3>(re, im, (const ull*)(gl + 0*24));
        gateP<4,2>(re, im, (const ull*)(gl + 1*24));
        gateP<4,1>(re, im, (const ull*)(gl + 2*24));
        gateP<4,0>(re, im, (const ull*)(gl + 3*24));
        gateLaneAll(re, im, (const ull*)(gl + 13*24));
        cnotP<4,3,2>(re, im); cnotP<4,2,1>(re, im); cnotP<4,1,0>(re, im);
        store16<9,10,11,12>(re, im, st, swz4(tid));
    }
    __syncthreads();
    pass_b(st, gmat, tid);               __syncthreads();
    pass_c(st, gmat, g8tab, tid);        __syncthreads();

    // --- layer 3 ---
    pass_a(st, gmat + NQ*24, tid, true);       __syncthreads();
    pass_b(st, gmat + NQ*24, tid);             __syncthreads();
    pass_c(st, gmat + NQ*24, g8tab + 48, tid); __syncthreads();

    // --- layer 4: A(carry), B, then C fused with readout ---
    {
        const float* gl = gmat + 2 * NQ * 24;
        const float* g8 = g8tab + 2 * 48;
        pass_a(st, gl, tid, true);  __syncthreads();
        pass_b(st, gl, tid);        __syncthreads();

        int pjb = swz4(tid << 4);
        ull re[16], im[16];
        load16<0,1,2,3>(re, im, st, pjb);
        gateShfl(re, im, (const ull*)(g8 + (tid & 1) * 12));
        gateP<4,3>(re, im, (const ull*)(gl + 9*24));
        gateP<4,2>(re, im, (const ull*)(gl + 10*24));
        gateP<4,1>(re, im, (const ull*)(gl + 11*24));
        gateP<4,0>(re, im, (const ull*)(gl + 12*24));

        ull accP = 0, acc9 = 0, acc10 = 0, acc11 = 0, acc12 = 0;
        const ull NEG1 = 0xBF800000BF800000ull;
#pragma unroll
        for (int k = 0; k < 16; ++k) {
            ull p = f2fma(im[k], im[k], f2mul(re[k], re[k]));
            accP = f2add(accP, p);
            int k3 = (k >> 3) & 1;
            int k23 = ((k >> 2) ^ (k >> 3)) & 1;
            int k123 = ((k >> 1) ^ (k >> 2) ^ (k >> 3)) & 1;
            int kpar = __popc(k) & 1;
            acc9  = k3   ? f2fma(p, NEG1, acc9)  : f2add(acc9,  p);
            acc10 = k23  ? f2fma(p, NEG1, acc10) : f2add(acc10, p);
            acc11 = k123 ? f2fma(p, NEG1, acc11) : f2add(acc11, p);
            acc12 = kpar ? f2fma(p, NEG1, acc12) : f2add(acc12, p);
        }
        float z[NQ];
        {
            float Pl, Ph;  upk(accP, Pl, Ph);   float Ps = Pl + Ph;
            float l9, h9;  upk(acc9, l9, h9);
            float l10,h10; upk(acc10,l10,h10);
            float l11,h11; upk(acc11,l11,h11);
            float l12,h12; upk(acc12,l12,h12);
            int t01 = (tid ^ (tid >> 1)) & 1;
            float f5 = t01 ? -1.f : 1.f;
            z[1] = (tid & 128) ? -Ps : Ps;
            z[2] = (tid & 64)  ? -Ps : Ps;
            z[3] = (tid & 32)  ? -Ps : Ps;
            z[4] = (tid & 16)  ? -Ps : Ps;
            z[5] = (tid & 8)   ? -Ps : Ps;
            z[6] = (tid & 4)   ? -Ps : Ps;
            z[7] = (tid & 2)   ? -Ps : Ps;
            z[8] = t01 ? -Ps : Ps;
            z[9]  = f5 * (l9  + h9);
            z[10] = f5 * (l10 + h10);
            z[11] = f5 * (l11 + h11);
            z[12] = f5 * (l12 + h12);
            z[13] = f5 * (l12 - h12);
            z[0]  = (tid & 256) ? -z[13] : z[13];
        }

#pragma unroll
        for (int w = 0; w < NQ; ++w)
#pragma unroll
            for (int o = 16; o; o >>= 1)
                z[w] += __shfl_xor_sync(0xffffffffu, z[w], o);

        __syncthreads();
        if ((tid & 31) == 0) {
            int wr = tid >> 5;
#pragma unroll
            for (int w = 0; w < NQ; ++w) red[wr*NQ + w] = z[w];
        }
        __syncthreads();
        if (tid < NQ) {
            float s = 0.f;
#pragma unroll
            for (int wr = 0; wr < NT/32; ++wr) s += red[wr*NQ + tid];
            red[224 + tid] = s * w_out[tid];
        }
        __syncthreads();
        if (tid == 0) {
            float o = b_out[0];
#pragma unroll
            for (int w = 0; w < NQ; ++w) o += red[224 + w];
            out[b] = o;
        }
    }
}

extern "C" void kernel_launch(void* const* d_in, const int* in_sizes, int n_in,
                              void* d_out, int out_size)
{
    const float* x     = (const float*)d_in[0];
    const float* w_in  = (const float*)d_in[1];
    const float* b_in  = (const float*)d_in[2];
    const float* wts   = (const float*)d_in[3];
    const float* w_out = (const float*)d_in[4];
    const float* b_out = (const float*)d_in[5];
    float* out = (float*)d_out;

    const int B = in_sizes[0] / SEQL;
    const int smem = (2*DIM + 42*24 + 144 + 28 + 240) * (int)sizeof(float);

    cudaFuncSetAttribute(vqc_kernel, cudaFuncAttributeMaxDynamicSharedMemorySize, smem);
    vqc_kernel<<<B, NT, smem>>>(x, w_in, b_in, wts, w_out, b_out, out);
}

// round 14
// speedup vs baseline: 1.0651x; 1.0651x over previous
#include <cuda_runtime.h>
#include <cstdint>

#define NQ   14
#define NL   4
#define DIM  16384
#define NT   512
#define SEQL 8

typedef unsigned long long ull;

__device__ __forceinline__ ull f2mul(ull a, ull b) {
    ull d; asm("mul.rn.f32x2 %0, %1, %2;" : "=l"(d) : "l"(a), "l"(b)); return d;
}
__device__ __forceinline__ ull f2fma(ull a, ull b, ull c) {
    ull d; asm("fma.rn.f32x2 %0, %1, %2, %3;" : "=l"(d) : "l"(a), "l"(b), "l"(c)); return d;
}
__device__ __forceinline__ ull f2add(ull a, ull b) {
    ull d; asm("add.rn.f32x2 %0, %1, %2;" : "=l"(d) : "l"(a), "l"(b)); return d;
}
__device__ __forceinline__ ull pk(float lo, float hi) {
    ull r; asm("mov.b64 %0, {%1, %2};" : "=l"(r) : "f"(lo), "f"(hi)); return r;
}
__device__ __forceinline__ void upk(ull v, float& lo, float& hi) {
    asm("mov.b64 {%0, %1}, %2;" : "=f"(lo), "=f"(hi) : "l"(v));
}
__device__ __forceinline__ ull lswap(ull v) {
    float lo, hi; upk(v, lo, hi); return pk(hi, lo);
}

__device__ __forceinline__ int swz4(int j) { return j ^ ((j >> 4) & 15); }

// 7-coeff SU(2) packed butterfly (correctness-proven in R11):
// u00=X+iY, u01=Z+iW, u10=-conj(u01), u11=conj(u00)
// table ull idx: 0:X 1:Y 2:-Y 3:Z 4:-Z 5:W 6:-W (duplicated pairs, 16-float slot)
template<int NB, int J>
__device__ __forceinline__ void gateP7(ull* re, ull* im, const ull* g) {
    ull X = g[0], Y = g[1], nY = g[2], Z = g[3], nZ = g[4], W = g[5], nW = g[6];
#pragma unroll
    for (int k = 0; k < (1 << NB); ++k)
        if (!(k & (1 << J))) {
            const int m = k | (1 << J);
            ull p0r = re[k], p0i = im[k], p1r = re[m], p1i = im[m];
            ull n0r = f2fma(nW, p1i, f2fma(Z, p1r, f2fma(nY, p0i, f2mul(X, p0r))));
            ull n0i = f2fma(W,  p1r, f2fma(Z, p1i, f2fma(Y,  p0r, f2mul(X, p0i))));
            ull n1r = f2fma(Y,  p1i, f2fma(X, p1r, f2fma(nW, p0i, f2mul(nZ, p0r))));
            ull n1i = f2fma(nY, p1r, f2fma(X, p1i, f2fma(W,  p0r, f2mul(nZ, p0i))));
            re[k] = n0r; im[k] = n0i; re[m] = n1r; im[m] = n1i;
        }
}

template<int NB, int JC, int JT>
__device__ __forceinline__ void cnotP(ull* re, ull* im) {
#pragma unroll
    for (int k = 0; k < (1 << NB); ++k)
        if ((k & (1 << JC)) && !(k & (1 << JT))) {
            const int m = k | (1 << JT);
            ull t = re[k]; re[k] = re[m]; re[m] = t;
            t = im[k]; im[k] = im[m]; im[m] = t;
        }
}

template<int NB, int JT>
__device__ __forceinline__ void cswapHalf(ull* re, ull* im, bool pred) {
    if (pred) {
#pragma unroll
        for (int k = 0; k < (1 << NB); ++k)
            if (!(k & (1 << JT))) {
                const int m = k | (1 << JT);
                ull t = re[k]; re[k] = re[m]; re[m] = t;
                t = im[k]; im[k] = im[m]; im[m] = t;
            }
    }
}

template<int J0,int J1,int J2,int J3>
__device__ __forceinline__ void load16(ull* re, ull* im,
                                       const ull* reP, const ull* imP, int pjb) {
#pragma unroll
    for (int k = 0; k < 16; ++k) {
        int joff = ((k&1)?(1<<J0):0) | ((k&2)?(1<<J1):0)
                 | ((k&4)?(1<<J2):0) | ((k&8)?(1<<J3):0);
        int a = pjb ^ (joff ^ ((joff >> 4) & 15));
        re[k] = reP[a]; im[k] = imP[a];
    }
}
template<int J0,int J1,int J2,int J3>
__device__ __forceinline__ void store16(const ull* re, const ull* im,
                                        ull* reP, ull* imP, int pjb) {
#pragma unroll
    for (int k = 0; k < 16; ++k) {
        int joff = ((k&1)?(1<<J0):0) | ((k&2)?(1<<J1):0)
                 | ((k&4)?(1<<J2):0) | ((k&8)?(1<<J3):0);
        int a = pjb ^ (joff ^ ((joff >> 4) & 15));
        reP[a] = re[k]; imP[a] = im[k];
    }
}

__device__ __forceinline__ float2 cmulf(float2 a, float2 b) {
    return make_float2(a.x*b.x - a.y*b.y, a.x*b.y + a.y*b.x);
}

// wire-13 (amp0 lane) butterfly; table ull idx: 0:C1 1:C2 2:nC2 3:C3 4:C4 5:nC4
__device__ __forceinline__ void gateLaneAll(ull* re, ull* im, const ull* g13) {
    ull C1 = g13[0], C2 = g13[1], nC2 = g13[2],
        C3 = g13[3], C4 = g13[4], nC4 = g13[5];
#pragma unroll
    for (int k = 0; k < 16; ++k) {
        ull qr = lswap(re[k]), qi = lswap(im[k]);
        ull nr = f2fma(C4,  qi, f2fma(C3, qr, f2fma(C2,  im[k], f2mul(C1, re[k]))));
        ull ni = f2fma(nC4, qr, f2fma(C3, qi, f2fma(nC2, re[k], f2mul(C1, im[k]))));
        re[k] = nr; im[k] = ni;
    }
}

__device__ __forceinline__ void carriedSwap(ull* re, ull* im) {
#pragma unroll
    for (int k1 = 0; k1 < 8; ++k1) {
        float alo, ahi, blo, bhi;
        upk(re[k1], alo, ahi); upk(re[k1|8], blo, bhi);
        re[k1] = pk(alo, bhi); re[k1|8] = pk(blo, ahi);
        upk(im[k1], alo, ahi); upk(im[k1|8], blo, bhi);
        im[k1] = pk(alo, bhi); im[k1|8] = pk(blo, ahi);
    }
}

__device__ __forceinline__ void gateShfl(ull* re, ull* im, const ull* gr) {
    ull Ax = gr[0], Ay = gr[1], nAy = gr[2], Az = gr[3], Aw = gr[4], nAw = gr[5];
#pragma unroll
    for (int k = 0; k < 16; ++k) {
        ull qr = __shfl_xor_sync(0xffffffffu, re[k], 1);
        ull qi = __shfl_xor_sync(0xffffffffu, im[k], 1);
        ull nr = f2fma(nAw, qi, f2fma(Az, qr, f2fma(nAy, im[k], f2mul(Ax, re[k]))));
        ull ni = f2fma(Aw,  qr, f2fma(Az, qi, f2fma(Ay,  re[k], f2mul(Ax, im[k]))));
        re[k] = nr; im[k] = ni;
    }
}

// gmat slots: 16 floats per (layer, wire); gateP7 uses 7 ulls, lane gate 6 ulls
__device__ __forceinline__ void pass_a(ull* reP, ull* imP, const float* gl,
                                       int tid, bool carry) {
    int pjb = swz4(tid);
    ull re[16], im[16];
    load16<9,10,11,12>(re, im, reP, imP, pjb);
    if (carry) carriedSwap(re, im);
    gateP7<4,3>(re, im, (const ull*)(gl + 0*16));
    gateP7<4,2>(re, im, (const ull*)(gl + 1*16));
    gateP7<4,1>(re, im, (const ull*)(gl + 2*16));
    gateP7<4,0>(re, im, (const ull*)(gl + 3*16));
    gateLaneAll(re, im, (const ull*)(gl + 13*16));
    cnotP<4,3,2>(re, im); cnotP<4,2,1>(re, im); cnotP<4,1,0>(re, im);
    store16<9,10,11,12>(re, im, reP, imP, pjb);
}
__device__ __forceinline__ void pass_b(ull* reP, ull* imP, const float* gl, int tid) {
    int base = (tid & 31) | ((tid >> 5) << 9);
    int pjb = swz4(base);
    ull re[16], im[16];
    load16<5,6,7,8>(re, im, reP, imP, pjb);
    gateP7<4,3>(re, im, (const ull*)(gl + 4*16));
    gateP7<4,2>(re, im, (const ull*)(gl + 5*16));
    gateP7<4,1>(re, im, (const ull*)(gl + 6*16));
    gateP7<4,0>(re, im, (const ull*)(gl + 7*16));
    cswapHalf<4,3>(re, im, (tid >> 5) & 1);
    cnotP<4,3,2>(re, im); cnotP<4,2,1>(re, im); cnotP<4,1,0>(re, im);
    store16<5,6,7,8>(re, im, reP, imP, pjb);
}
__device__ __forceinline__ void pass_c(ull* reP, ull* imP, const float* gl,
                                       const float* g8, int tid) {
    int pjb = swz4(tid << 4);
    ull re[16], im[16];
    load16<0,1,2,3>(re, im, reP, imP, pjb);
    gateShfl(re, im, (const ull*)(g8 + (tid & 3) * 12));
    gateP7<4,3>(re, im, (const ull*)(gl + 9*16));
    gateP7<4,2>(re, im, (const ull*)(gl + 10*16));
    gateP7<4,1>(re, im, (const ull*)(gl + 11*16));
    gateP7<4,0>(re, im, (const ull*)(gl + 12*16));
    cswapHalf<4,3>(re, im, tid & 1);
    cnotP<4,3,2>(re, im); cnotP<4,2,1>(re, im); cnotP<4,1,0>(re, im);
#pragma unroll
    for (int k = 1; k < 16; k += 2) { re[k] = lswap(re[k]); im[k] = lswap(im[k]); }
    store16<0,1,2,3>(re, im, reP, imP, pjb);
}

__global__ void __launch_bounds__(NT, 1)
vqc_kernel(const float* __restrict__ x,    const float* __restrict__ w_in,
           const float* __restrict__ b_in, const float* __restrict__ wts,
           const float* __restrict__ w_out,const float* __restrict__ b_out,
           float* __restrict__ out)
{
    extern __shared__ float smem[];
    float* reF   = smem;
    float* imF   = smem + DIM;
    float* gmat  = smem + 2 * DIM;          // 42*16 = 672
    float* g8tab = gmat + 42 * 16;          // 144
    float* enc   = g8tab + 144;             // 28
    float* red   = enc + 28;                // 240
    ull* reP = (ull*)reF;
    ull* imP = (ull*)imF;
    float2* ftab = (float2*)red;            // init factor table (56 floats)

    const int b = blockIdx.x, tid = threadIdx.x;

    if (tid < NQ) {
        float acc = b_in[tid];
#pragma unroll
        for (int s2 = 0; s2 < SEQL; ++s2) acc += x[b*SEQL + s2] * w_in[tid*SEQL + s2];
        enc[2*tid]     = cospif(0.5f * acc);
        enc[2*tid + 1] = sinpif(0.5f * acc);
    }
    __syncthreads();

    if (tid < NQ * NL) {
        int i = tid % NQ, j = tid / NQ;
        const float* w = wts + (i*NL + j)*3;
        float cx = cosf(0.5f*w[0]), sx = sinf(0.5f*w[0]);
        float cy = cosf(0.5f*w[1]), sy = sinf(0.5f*w[1]);
        float cz = cosf(0.5f*w[2]), sz = sinf(0.5f*w[2]);
        if (j == 3) { cz = 1.f; sz = 0.f; }
        float2 m00 = make_float2( cy*cx,  sy*sx);
        float2 m01 = make_float2(-sy*cx, -cy*sx);
        float2 e0 = make_float2(cz, -sz);
        float2 u00 = cmulf(e0, m00), u01 = cmulf(e0, m01);
        float X = u00.x, Y = u00.y, Z = u01.x, W = u01.y;
        float2 u10 = make_float2(-Z, W);   // -conj(u01)
        float2 u11 = make_float2(X, -Y);   //  conj(u00)
        if (j == 0) {
            float c = enc[2*i], s = enc[2*i+1];
            int t = 13 - i;
            ftab[t*2 + 0] = make_float2(X*c + Z*s,      Y*c + W*s);
            ftab[t*2 + 1] = make_float2(u10.x*c + u11.x*s, u10.y*c + u11.y*s);
        } else if (i == 8) {
            float2 Ca[4] = { u00, u11, u10, u01 };
            float2 Cb[4] = { u01, u10, u11, u00 };
#pragma unroll
            for (int s4 = 0; s4 < 4; ++s4) {
                float* r = g8tab + ((j-1)*4 + s4)*12;
                r[0]=Ca[s4].x; r[1]=Ca[s4].x;  r[2]=Ca[s4].y; r[3]=Ca[s4].y;
                r[4]=-Ca[s4].y; r[5]=-Ca[s4].y; r[6]=Cb[s4].x; r[7]=Cb[s4].x;
                r[8]=Cb[s4].y; r[9]=Cb[s4].y;  r[10]=-Cb[s4].y; r[11]=-Cb[s4].y;
            }
        } else {
            float* g = gmat + ((j-1)*NQ + i)*16;
            if (i < 13) {   // 7-coeff SU(2) table: X Y -Y Z -Z W -W (dup pairs)
                g[0]=X;  g[1]=X;   g[2]=Y;  g[3]=Y;   g[4]=-Y; g[5]=-Y;
                g[6]=Z;  g[7]=Z;   g[8]=-Z; g[9]=-Z;  g[10]=W; g[11]=W;
                g[12]=-W; g[13]=-W; g[14]=0.f; g[15]=0.f;
            } else {        // wire 13 lane-distinct: C1 C2 nC2 C3 C4 nC4
                g[0]=X;  g[1]=X;   g[2]=-Y; g[3]=Y;   g[4]=Y;  g[5]=-Y;
                g[6]=Z;  g[7]=-Z;  g[8]=-W; g[9]=-W;  g[10]=W; g[11]=W;
                g[12]=0.f; g[13]=0.f; g[14]=0.f; g[15]=0.f;
            }
        }
    }
    __syncthreads();

    // --- layer 2 pass A fused with init: synthesize amps in registers.
    {
        const float* gl = gmat;
        int gx = tid ^ (tid >> 1);
        float2 P8 = ftab[2 + (gx & 1)];
#pragma unroll
        for (int t = 2; t <= 8; ++t)
            P8 = cmulf(P8, ftab[t*2 + ((gx >> (t-1)) & 1)]);
        float2 Bl0 = cmulf(P8, ftab[0 + (tid & 1)]);
        float2 Bl1 = cmulf(P8, ftab[0 + ((tid & 1) ^ 1)]);
        float2 G00 = cmulf(ftab[24], ftab[26]);
        float2 G01 = cmulf(ftab[24], ftab[27]);
        float2 G10 = cmulf(ftab[25], ftab[26]);
        float2 G11 = cmulf(ftab[25], ftab[27]);
        int t8 = (tid >> 8) & 1;
        ull re[16], im[16];
#pragma unroll
        for (int k = 0; k < 16; ++k) {
            const int k0 = k & 1, k1 = (k >> 1) & 1, k2 = (k >> 2) & 1, k3 = (k >> 3) & 1;
            float2 H3 = cmulf(cmulf(ftab[18 + (t8 ^ k0)], ftab[20 + (k0 ^ k1)]),
                              ftab[22 + (k1 ^ k2)]);
            const int a0 = k2 ^ k3, b0c = k3;
            float2 HL0 = cmulf(H3, a0 ? (b0c ? G11 : G10) : (b0c ? G01 : G00));
            float2 HL1 = cmulf(H3, (a0^1) ? ((b0c^1) ? G11 : G10) : ((b0c^1) ? G01 : G00));
            float2 lo = cmulf(Bl0, HL0);
            float2 hi = cmulf(Bl1, HL1);
            re[k] = pk(lo.x, hi.x);
            im[k] = pk(lo.y, hi.y);
        }
        gateP7<4,3>(re, im, (const ull*)(gl + 0*16));
        gateP7<4,2>(re, im, (const ull*)(gl + 1*16));
        gateP7<4,1>(re, im, (const ull*)(gl + 2*16));
        gateP7<4,0>(re, im, (const ull*)(gl + 3*16));
        gateLaneAll(re, im, (const ull*)(gl + 13*16));
        cnotP<4,3,2>(re, im); cnotP<4,2,1>(re, im); cnotP<4,1,0>(re, im);
        store16<9,10,11,12>(re, im, reP, imP, swz4(tid));
    }
    __syncthreads();
    pass_b(reP, imP, gmat, tid);              __syncthreads();
    pass_c(reP, imP, gmat, g8tab, tid);       __syncthreads();

    // --- layer 3 ---
    pass_a(reP, imP, gmat + NQ*16, tid, true);      __syncthreads();
    pass_b(reP, imP, gmat + NQ*16, tid);            __syncthreads();
    pass_c(reP, imP, gmat + NQ*16, g8tab + 48, tid);__syncthreads();

    // --- layer 4: A(carry), B, then C fused with readout ---
    {
        const float* gl = gmat + 2 * NQ * 16;
        const float* g8 = g8tab + 2 * 48;
        pass_a(reP, imP, gl, tid, true);  __syncthreads();
        pass_b(reP, imP, gl, tid);        __syncthreads();

        int pjb = swz4(tid << 4);
        ull re[16], im[16];
        load16<0,1,2,3>(re, im, reP, imP, pjb);
        gateShfl(re, im, (const ull*)(g8 + (tid & 1) * 12));
        gateP7<4,3>(re, im, (const ull*)(gl + 9*16));
        gateP7<4,2>(re, im, (const ull*)(gl + 10*16));
        gateP7<4,1>(re, im, (const ull*)(gl + 11*16));
        gateP7<4,0>(re, im, (const ull*)(gl + 12*16));

        ull accP = 0, acc9 = 0, acc10 = 0, acc11 = 0, acc12 = 0;
        const ull NEG1 = 0xBF800000BF800000ull;
#pragma unroll
        for (int k = 0; k < 16; ++k) {
            ull p = f2fma(im[k], im[k], f2mul(re[k], re[k]));
            accP = f2add(accP, p);
            int k3 = (k >> 3) & 1;
            int k23 = ((k >> 2) ^ (k >> 3)) & 1;
            int k123 = ((k >> 1) ^ (k >> 2) ^ (k >> 3)) & 1;
            int kpar = __popc(k) & 1;
            acc9  = k3   ? f2fma(p, NEG1, acc9)  : f2add(acc9,  p);
            acc10 = k23  ? f2fma(p, NEG1, acc10) : f2add(acc10, p);
            acc11 = k123 ? f2fma(p, NEG1, acc11) : f2add(acc11, p);
            acc12 = kpar ? f2fma(p, NEG1, acc12) : f2add(acc12, p);
        }
        float z[NQ];
        {
            float Pl, Ph;  upk(accP, Pl, Ph);   float Ps = Pl + Ph;
            float l9, h9;  upk(acc9, l9, h9);
            float l10,h10; upk(acc10,l10,h10);
            float l11,h11; upk(acc11,l11,h11);
            float l12,h12; upk(acc12,l12,h12);
            int t01 = (tid ^ (tid >> 1)) & 1;
            float f5 = t01 ? -1.f : 1.f;
            z[1] = (tid & 128) ? -Ps : Ps;
            z[2] = (tid & 64)  ? -Ps : Ps;
            z[3] = (tid & 32)  ? -Ps : Ps;
            z[4] = (tid & 16)  ? -Ps : Ps;
            z[5] = (tid & 8)   ? -Ps : Ps;
            z[6] = (tid & 4)   ? -Ps : Ps;
            z[7] = (tid & 2)   ? -Ps : Ps;
            z[8] = t01 ? -Ps : Ps;
            z[9]  = f5 * (l9  + h9);
            z[10] = f5 * (l10 + h10);
            z[11] = f5 * (l11 + h11);
            z[12] = f5 * (l12 + h12);
            z[13] = f5 * (l12 - h12);
            z[0]  = (tid & 256) ? -z[13] : z[13];
        }

#pragma unroll
        for (int w = 0; w < NQ; ++w)
#pragma unroll
            for (int o = 16; o; o >>= 1)
                z[w] += __shfl_xor_sync(0xffffffffu, z[w], o);

        __syncthreads();
        if ((tid & 31) == 0) {
            int wr = tid >> 5;
#pragma unroll
            for (int w = 0; w < NQ; ++w) red[wr*NQ + w] = z[w];
        }
        __syncthreads();
        if (tid < NQ) {
            float s = 0.f;
#pragma unroll
            for (int wr = 0; wr < NT/32; ++wr) s += red[wr*NQ + tid];
            red[224 + tid] = s * w_out[tid];
        }
        __syncthreads();
        if (tid == 0) {
            float o = b_out[0];
#pragma unroll
            for (int w = 0; w < NQ; ++w) o += red[224 + w];
            out[b] = o;
        }
    }
}

extern "C" void kernel_launch(void* const* d_in, const int* in_sizes, int n_in,
                              void* d_out, int out_size)
{
    const float* x     = (const float*)d_in[0];
    const float* w_in  = (const float*)d_in[1];
    const float* b_in  = (const float*)d_in[2];
    const float* wts   = (const float*)d_in[3];
    const float* w_out = (const float*)d_in[4];
    const float* b_out = (const float*)d_in[5];
    float* out = (float*)d_out;

    const int B = in_sizes[0] / SEQL;
    const int smem = (2*DIM + 42*16 + 144 + 28 + 240) * (int)sizeof(float);

    cudaFuncSetAttribute(vqc_kernel, cudaFuncAttributeMaxDynamicSharedMemorySize, smem);
    vqc_kernel<<<B, NT, smem>>>(x, w_in, b_in, wts, w_out, b_out, out);
}

// round 15
// speedup vs baseline: 1.0671x; 1.0019x over previous
#include <cuda_runtime.h>
#include <cstdint>

#define NQ   14
#define NL   4
#define DIM  16384
#define NT   512
#define SEQL 8

typedef unsigned long long ull;

__device__ __forceinline__ ull f2mul(ull a, ull b) {
    ull d; asm("mul.rn.f32x2 %0, %1, %2;" : "=l"(d) : "l"(a), "l"(b)); return d;
}
__device__ __forceinline__ ull f2fma(ull a, ull b, ull c) {
    ull d; asm("fma.rn.f32x2 %0, %1, %2, %3;" : "=l"(d) : "l"(a), "l"(b), "l"(c)); return d;
}
__device__ __forceinline__ ull f2add(ull a, ull b) {
    ull d; asm("add.rn.f32x2 %0, %1, %2;" : "=l"(d) : "l"(a), "l"(b)); return d;
}
__device__ __forceinline__ ull pk(float lo, float hi) {
    ull r; asm("mov.b64 %0, {%1, %2};" : "=l"(r) : "f"(lo), "f"(hi)); return r;
}
__device__ __forceinline__ void upk(ull v, float& lo, float& hi) {
    asm("mov.b64 {%0, %1}, %2;" : "=f"(lo), "=f"(hi) : "l"(v));
}
__device__ __forceinline__ ull lswap(ull v) {
    float lo, hi; upk(v, lo, hi); return pk(hi, lo);
}

__device__ __forceinline__ int swz4(int j) { return j ^ ((j >> 4) & 15); }

// 7-coeff SU(2) packed butterfly; coefficients fetched via LDS.128 pairs.
// table ull idx: 0:X 1:Y 2:-Y 3:Z 4:-Z 5:W 6:-W (duplicated pairs, 16-float slot,
// 16B-aligned)
template<int NB, int J>
__device__ __forceinline__ void gateP7(ull* re, ull* im, const float* gf) {
    const ulonglong2* g2 = (const ulonglong2*)gf;
    ulonglong2 v01 = g2[0], v23 = g2[1], v45 = g2[2];
    ull X = v01.x, Y = v01.y, nY = v23.x, Z = v23.y, nZ = v45.x, W = v45.y;
    ull nW = ((const ull*)gf)[6];
#pragma unroll
    for (int k = 0; k < (1 << NB); ++k)
        if (!(k & (1 << J))) {
            const int m = k | (1 << J);
            ull p0r = re[k], p0i = im[k], p1r = re[m], p1i = im[m];
            ull n0r = f2fma(nW, p1i, f2fma(Z, p1r, f2fma(nY, p0i, f2mul(X, p0r))));
            ull n0i = f2fma(W,  p1r, f2fma(Z, p1i, f2fma(Y,  p0r, f2mul(X, p0i))));
            ull n1r = f2fma(Y,  p1i, f2fma(X, p1r, f2fma(nW, p0i, f2mul(nZ, p0r))));
            ull n1i = f2fma(nY, p1r, f2fma(X, p1i, f2fma(W,  p0r, f2mul(nZ, p0i))));
            re[k] = n0r; im[k] = n0i; re[m] = n1r; im[m] = n1i;
        }
}

template<int NB, int JC, int JT>
__device__ __forceinline__ void cnotP(ull* re, ull* im) {
#pragma unroll
    for (int k = 0; k < (1 << NB); ++k)
        if ((k & (1 << JC)) && !(k & (1 << JT))) {
            const int m = k | (1 << JT);
            ull t = re[k]; re[k] = re[m]; re[m] = t;
            t = im[k]; im[k] = im[m]; im[m] = t;
        }
}

template<int NB, int JT>
__device__ __forceinline__ void cswapHalf(ull* re, ull* im, bool pred) {
    if (pred) {
#pragma unroll
        for (int k = 0; k < (1 << NB); ++k)
            if (!(k & (1 << JT))) {
                const int m = k | (1 << JT);
                ull t = re[k]; re[k] = re[m]; re[m] = t;
                t = im[k]; im[k] = im[m]; im[m] = t;
            }
    }
}

template<int J0,int J1,int J2,int J3>
__device__ __forceinline__ void load16(ull* re, ull* im,
                                       const ull* reP, const ull* imP, int pjb) {
#pragma unroll
    for (int k = 0; k < 16; ++k) {
        int joff = ((k&1)?(1<<J0):0) | ((k&2)?(1<<J1):0)
                 | ((k&4)?(1<<J2):0) | ((k&8)?(1<<J3):0);
        int a = pjb ^ (joff ^ ((joff >> 4) & 15));
        re[k] = reP[a]; im[k] = imP[a];
    }
}
template<int J0,int J1,int J2,int J3>
__device__ __forceinline__ void store16(const ull* re, const ull* im,
                                        ull* reP, ull* imP, int pjb) {
#pragma unroll
    for (int k = 0; k < 16; ++k) {
        int joff = ((k&1)?(1<<J0):0) | ((k&2)?(1<<J1):0)
                 | ((k&4)?(1<<J2):0) | ((k&8)?(1<<J3):0);
        int a = pjb ^ (joff ^ ((joff >> 4) & 15));
        reP[a] = re[k]; imP[a] = im[k];
    }
}

__device__ __forceinline__ float2 cmulf(float2 a, float2 b) {
    return make_float2(a.x*b.x - a.y*b.y, a.x*b.y + a.y*b.x);
}

// wire-13 (amp0 lane) butterfly; table ull idx: 0:C1 1:C2 2:nC2 3:C3 4:C4 5:nC4
__device__ __forceinline__ void gateLaneAll(ull* re, ull* im, const float* gf) {
    const ulonglong2* g2 = (const ulonglong2*)gf;
    ulonglong2 v01 = g2[0], v23 = g2[1], v45 = g2[2];
    ull C1 = v01.x, C2 = v01.y, nC2 = v23.x, C3 = v23.y, C4 = v45.x, nC4 = v45.y;
#pragma unroll
    for (int k = 0; k < 16; ++k) {
        ull qr = lswap(re[k]), qi = lswap(im[k]);
        ull nr = f2fma(C4,  qi, f2fma(C3, qr, f2fma(C2,  im[k], f2mul(C1, re[k]))));
        ull ni = f2fma(nC4, qr, f2fma(C3, qi, f2fma(nC2, re[k], f2mul(C1, im[k]))));
        re[k] = nr; im[k] = ni;
    }
}

__device__ __forceinline__ void carriedSwap(ull* re, ull* im) {
#pragma unroll
    for (int k1 = 0; k1 < 8; ++k1) {
        float alo, ahi, blo, bhi;
        upk(re[k1], alo, ahi); upk(re[k1|8], blo, bhi);
        re[k1] = pk(alo, bhi); re[k1|8] = pk(blo, ahi);
        upk(im[k1], alo, ahi); upk(im[k1|8], blo, bhi);
        im[k1] = pk(alo, bhi); im[k1|8] = pk(blo, ahi);
    }
}

// wire-8 shuffle butterfly (partner = tid^1); row table 12-float (48B) slots,
// 16B-aligned; coeff ull idx: 0:Ax 1:Ay 2:nAy 3:Az 4:Aw 5:nAw
__device__ __forceinline__ void gateShfl(ull* re, ull* im, const float* gf) {
    const ulonglong2* g2 = (const ulonglong2*)gf;
    ulonglong2 v01 = g2[0], v23 = g2[1], v45 = g2[2];
    ull Ax = v01.x, Ay = v01.y, nAy = v23.x, Az = v23.y, Aw = v45.x, nAw = v45.y;
#pragma unroll
    for (int k = 0; k < 16; ++k) {
        ull qr = __shfl_xor_sync(0xffffffffu, re[k], 1);
        ull qi = __shfl_xor_sync(0xffffffffu, im[k], 1);
        ull nr = f2fma(nAw, qi, f2fma(Az, qr, f2fma(nAy, im[k], f2mul(Ax, re[k]))));
        ull ni = f2fma(Aw,  qr, f2fma(Az, qi, f2fma(Ay,  re[k], f2mul(Ax, im[k]))));
        re[k] = nr; im[k] = ni;
    }
}

__device__ __forceinline__ void pass_a(ull* reP, ull* imP, const float* gl,
                                       int tid, bool carry) {
    int pjb = swz4(tid);
    ull re[16], im[16];
    load16<9,10,11,12>(re, im, reP, imP, pjb);
    if (carry) carriedSwap(re, im);
    gateP7<4,3>(re, im, gl + 0*16);
    gateP7<4,2>(re, im, gl + 1*16);
    gateP7<4,1>(re, im, gl + 2*16);
    gateP7<4,0>(re, im, gl + 3*16);
    gateLaneAll(re, im, gl + 13*16);
    cnotP<4,3,2>(re, im); cnotP<4,2,1>(re, im); cnotP<4,1,0>(re, im);
    store16<9,10,11,12>(re, im, reP, imP, pjb);
}
__device__ __forceinline__ void pass_b(ull* reP, ull* imP, const float* gl, int tid) {
    int base = (tid & 31) | ((tid >> 5) << 9);
    int pjb = swz4(base);
    ull re[16], im[16];
    load16<5,6,7,8>(re, im, reP, imP, pjb);
    gateP7<4,3>(re, im, gl + 4*16);
    gateP7<4,2>(re, im, gl + 5*16);
    gateP7<4,1>(re, im, gl + 6*16);
    gateP7<4,0>(re, im, gl + 7*16);
    cswapHalf<4,3>(re, im, (tid >> 5) & 1);
    cnotP<4,3,2>(re, im); cnotP<4,2,1>(re, im); cnotP<4,1,0>(re, im);
    store16<5,6,7,8>(re, im, reP, imP, pjb);
}
__device__ __forceinline__ void pass_c(ull* reP, ull* imP, const float* gl,
                                       const float* g8, int tid) {
    int pjb = swz4(tid << 4);
    ull re[16], im[16];
    load16<0,1,2,3>(re, im, reP, imP, pjb);
    gateShfl(re, im, g8 + (tid & 3) * 12);
    gateP7<4,3>(re, im, gl + 9*16);
    gateP7<4,2>(re, im, gl + 10*16);
    gateP7<4,1>(re, im, gl + 11*16);
    gateP7<4,0>(re, im, gl + 12*16);
    cswapHalf<4,3>(re, im, tid & 1);
    cnotP<4,3,2>(re, im); cnotP<4,2,1>(re, im); cnotP<4,1,0>(re, im);
#pragma unroll
    for (int k = 1; k < 16; k += 2) { re[k] = lswap(re[k]); im[k] = lswap(im[k]); }
    store16<0,1,2,3>(re, im, reP, imP, pjb);
}

__global__ void __launch_bounds__(NT, 1)
vqc_kernel(const float* __restrict__ x,    const float* __restrict__ w_in,
           const float* __restrict__ b_in, const float* __restrict__ wts,
           const float* __restrict__ w_out,const float* __restrict__ b_out,
           float* __restrict__ out)
{
    extern __shared__ float smem[];
    float* reF   = smem;
    float* imF   = smem + DIM;
    float* gmat  = smem + 2 * DIM;          // 42*16 = 672 (slots 64B-strided)
    float* g8tab = gmat + 42 * 16;          // 144 (slots 48B-strided, 16B-aligned)
    float* enc   = g8tab + 144;             // 28
    float* red   = enc + 28;                // 240
    ull* reP = (ull*)reF;
    ull* imP = (ull*)imF;
    float2* ftab = (float2*)red;            // init factor table (56 floats)

    const int b = blockIdx.x, tid = threadIdx.x;

    if (tid < NQ) {
        float acc = b_in[tid];
#pragma unroll
        for (int s2 = 0; s2 < SEQL; ++s2) acc += x[b*SEQL + s2] * w_in[tid*SEQL + s2];
        enc[2*tid]     = cospif(0.5f * acc);
        enc[2*tid + 1] = sinpif(0.5f * acc);
    }
    __syncthreads();

    if (tid < NQ * NL) {
        int i = tid % NQ, j = tid / NQ;
        const float* w = wts + (i*NL + j)*3;
        float cx = cosf(0.5f*w[0]), sx = sinf(0.5f*w[0]);
        float cy = cosf(0.5f*w[1]), sy = sinf(0.5f*w[1]);
        float cz = cosf(0.5f*w[2]), sz = sinf(0.5f*w[2]);
        if (j == 3) { cz = 1.f; sz = 0.f; }
        float2 m00 = make_float2( cy*cx,  sy*sx);
        float2 m01 = make_float2(-sy*cx, -cy*sx);
        float2 e0 = make_float2(cz, -sz);
        float2 u00 = cmulf(e0, m00), u01 = cmulf(e0, m01);
        float X = u00.x, Y = u00.y, Z = u01.x, W = u01.y;
        float2 u10 = make_float2(-Z, W);   // -conj(u01)
        float2 u11 = make_float2(X, -Y);   //  conj(u00)
        if (j == 0) {
            float c = enc[2*i], s = enc[2*i+1];
            int t = 13 - i;
            ftab[t*2 + 0] = make_float2(X*c + Z*s,         Y*c + W*s);
            ftab[t*2 + 1] = make_float2(u10.x*c + u11.x*s, u10.y*c + u11.y*s);
        } else if (i == 8) {
            float2 Ca[4] = { u00, u11, u10, u01 };
            float2 Cb[4] = { u01, u10, u11, u00 };
#pragma unroll
            for (int s4 = 0; s4 < 4; ++s4) {
                float* r = g8tab + ((j-1)*4 + s4)*12;
                r[0]=Ca[s4].x; r[1]=Ca[s4].x;  r[2]=Ca[s4].y; r[3]=Ca[s4].y;
                r[4]=-Ca[s4].y; r[5]=-Ca[s4].y; r[6]=Cb[s4].x; r[7]=Cb[s4].x;
                r[8]=Cb[s4].y; r[9]=Cb[s4].y;  r[10]=-Cb[s4].y; r[11]=-Cb[s4].y;
            }
        } else {
            float* g = gmat + ((j-1)*NQ + i)*16;
            if (i < 13) {   // 7-coeff SU(2) table: X Y -Y Z -Z W -W (dup pairs)
                g[0]=X;  g[1]=X;   g[2]=Y;  g[3]=Y;   g[4]=-Y; g[5]=-Y;
                g[6]=Z;  g[7]=Z;   g[8]=-Z; g[9]=-Z;  g[10]=W; g[11]=W;
                g[12]=-W; g[13]=-W; g[14]=0.f; g[15]=0.f;
            } else {        // wire 13 lane-distinct: C1 C2 nC2 C3 C4 nC4
                g[0]=X;  g[1]=X;   g[2]=-Y; g[3]=Y;   g[4]=Y;  g[5]=-Y;
                g[6]=Z;  g[7]=-Z;  g[8]=-W; g[9]=-W;  g[10]=W; g[11]=W;
                g[12]=0.f; g[13]=0.f; g[14]=0.f; g[15]=0.f;
            }
        }
    }
    __syncthreads();

    // --- layer 2 pass A fused with init: synthesize amps in registers.
    {
        const float* gl = gmat;
        int gx = tid ^ (tid >> 1);
        float2 P8 = ftab[2 + (gx & 1)];
#pragma unroll
        for (int t = 2; t <= 8; ++t)
            P8 = cmulf(P8, ftab[t*2 + ((gx >> (t-1)) & 1)]);
        float2 Bl0 = cmulf(P8, ftab[0 + (tid & 1)]);
        float2 Bl1 = cmulf(P8, ftab[0 + ((tid & 1) ^ 1)]);
        float2 G00 = cmulf(ftab[24], ftab[26]);
        float2 G01 = cmulf(ftab[24], ftab[27]);
        float2 G10 = cmulf(ftab[25], ftab[26]);
        float2 G11 = cmulf(ftab[25], ftab[27]);
        int t8 = (tid >> 8) & 1;
        ull re[16], im[16];
#pragma unroll
        for (int k = 0; k < 16; ++k) {
            const int k0 = k & 1, k1 = (k >> 1) & 1, k2 = (k >> 2) & 1, k3 = (k >> 3) & 1;
            float2 H3 = cmulf(cmulf(ftab[18 + (t8 ^ k0)], ftab[20 + (k0 ^ k1)]),
                              ftab[22 + (k1 ^ k2)]);
            const int a0 = k2 ^ k3, b0c = k3;
            float2 HL0 = cmulf(H3, a0 ? (b0c ? G11 : G10) : (b0c ? G01 : G00));
            float2 HL1 = cmulf(H3, (a0^1) ? ((b0c^1) ? G11 : G10) : ((b0c^1) ? G01 : G00));
            float2 lo = cmulf(Bl0, HL0);
            float2 hi = cmulf(Bl1, HL1);
            re[k] = pk(lo.x, hi.x);
            im[k] = pk(lo.y, hi.y);
        }
        gateP7<4,3>(re, im, gl + 0*16);
        gateP7<4,2>(re, im, gl + 1*16);
        gateP7<4,1>(re, im, gl + 2*16);
        gateP7<4,0>(re, im, gl + 3*16);
        gateLaneAll(re, im, gl + 13*16);
        cnotP<4,3,2>(re, im); cnotP<4,2,1>(re, im); cnotP<4,1,0>(re, im);
        store16<9,10,11,12>(re, im, reP, imP, swz4(tid));
    }
    __syncthreads();
    pass_b(reP, imP, gmat, tid);              __syncthreads();
    pass_c(reP, imP, gmat, g8tab, tid);       __syncthreads();

    // --- layer 3 ---
    pass_a(reP, imP, gmat + NQ*16, tid, true);      __syncthreads();
    pass_b(reP, imP, gmat + NQ*16, tid);            __syncthreads();
    pass_c(reP, imP, gmat + NQ*16, g8tab + 48, tid);__syncthreads();

    // --- layer 4: A(carry), B, then C fused with readout ---
    {
        const float* gl = gmat + 2 * NQ * 16;
        const float* g8 = g8tab + 2 * 48;
        pass_a(reP, imP, gl, tid, true);  __syncthreads();
        pass_b(reP, imP, gl, tid);        __syncthreads();

        int pjb = swz4(tid << 4);
        ull re[16], im[16];
        load16<0,1,2,3>(re, im, reP, imP, pjb);
        gateShfl(re, im, g8 + (tid & 1) * 12);
        gateP7<4,3>(re, im, gl + 9*16);
        gateP7<4,2>(re, im, gl + 10*16);
        gateP7<4,1>(re, im, gl + 11*16);
        gateP7<4,0>(re, im, gl + 12*16);

        ull accP = 0, acc9 = 0, acc10 = 0, acc11 = 0, acc12 = 0;
        const ull NEG1 = 0xBF800000BF800000ull;
#pragma unroll
        for (int k = 0; k < 16; ++k) {
            ull p = f2fma(im[k], im[k], f2mul(re[k], re[k]));
            accP = f2add(accP, p);
            int k3 = (k >> 3) & 1;
            int k23 = ((k >> 2) ^ (k >> 3)) & 1;
            int k123 = ((k >> 1) ^ (k >> 2) ^ (k >> 3)) & 1;
            int kpar = __popc(k) & 1;
            acc9  = k3   ? f2fma(p, NEG1, acc9)  : f2add(acc9,  p);
            acc10 = k23  ? f2fma(p, NEG1, acc10) : f2add(acc10, p);
            acc11 = k123 ? f2fma(p, NEG1, acc11) : f2add(acc11, p);
            acc12 = kpar ? f2fma(p, NEG1, acc12) : f2add(acc12, p);
        }
        float z[NQ];
        {
            float Pl, Ph;  upk(accP, Pl, Ph);   float Ps = Pl + Ph;
            float l9, h9;  upk(acc9, l9, h9);
            float l10,h10; upk(acc10,l10,h10);
            float l11,h11; upk(acc11,l11,h11);
            float l12,h12; upk(acc12,l12,h12);
            int t01 = (tid ^ (tid >> 1)) & 1;
            float f5 = t01 ? -1.f : 1.f;
            z[1] = (tid & 128) ? -Ps : Ps;
            z[2] = (tid & 64)  ? -Ps : Ps;
            z[3] = (tid & 32)  ? -Ps : Ps;
            z[4] = (tid & 16)  ? -Ps : Ps;
            z[5] = (tid & 8)   ? -Ps : Ps;
            z[6] = (tid & 4)   ? -Ps : Ps;
            z[7] = (tid & 2)   ? -Ps : Ps;
            z[8] = t01 ? -Ps : Ps;
            z[9]  = f5 * (l9  + h9);
            z[10] = f5 * (l10 + h10);
            z[11] = f5 * (l11 + h11);
            z[12] = f5 * (l12 + h12);
            z[13] = f5 * (l12 - h12);
            z[0]  = (tid & 256) ? -z[13] : z[13];
        }

#pragma unroll
        for (int w = 0; w < NQ; ++w)
#pragma unroll
            for (int o = 16; o; o >>= 1)
                z[w] += __shfl_xor_sync(0xffffffffu, z[w], o);

        __syncthreads();
        if ((tid & 31) == 0) {
            int wr = tid >> 5;
#pragma unroll
            for (int w = 0; w < NQ; ++w) red[wr*NQ + w] = z[w];
        }
        __syncthreads();
        if (tid < NQ) {
            float s = 0.f;
#pragma unroll
            for (int wr = 0; wr < NT/32; ++wr) s += red[wr*NQ + tid];
            red[224 + tid] = s * w_out[tid];
        }
        __syncthreads();
        if (tid == 0) {
            float o = b_out[0];
#pragma unroll
            for (int w = 0; w < NQ; ++w) o += red[224 + w];
            out[b] = o;
        }
    }
}

extern "C" void kernel_launch(void* const* d_in, const int* in_sizes, int n_in,
                              void* d_out, int out_size)
{
    const float* x     = (const float*)d_in[0];
    const float* w_in  = (const float*)d_in[1];
    const float* b_in  = (const float*)d_in[2];
    const float* wts   = (const float*)d_in[3];
    const float* w_out = (const float*)d_in[4];
    const float* b_out = (const float*)d_in[5];
    float* out = (float*)d_out;

    const int B = in_sizes[0] / SEQL;
    const int smem = (2*DIM + 42*16 + 144 + 28 + 240) * (int)sizeof(float);

    cudaFuncSetAttribute(vqc_kernel, cudaFuncAttributeMaxDynamicSharedMemorySize, smem);
    vqc_kernel<<<B, NT, smem>>>(x, w_in, b_in, wts, w_out, b_out, out);
}

// round 16
// speedup vs baseline: 1.0815x; 1.0135x over previous
#include <cuda_runtime.h>
#include <cstdint>

#define NQ   14
#define NL   4
#define DIM  16384
#define NT   512
#define SEQL 8

typedef unsigned long long ull;

__device__ __forceinline__ ull f2mul(ull a, ull b) {
    ull d; asm("mul.rn.f32x2 %0, %1, %2;" : "=l"(d) : "l"(a), "l"(b)); return d;
}
__device__ __forceinline__ ull f2fma(ull a, ull b, ull c) {
    ull d; asm("fma.rn.f32x2 %0, %1, %2, %3;" : "=l"(d) : "l"(a), "l"(b), "l"(c)); return d;
}
__device__ __forceinline__ ull f2add(ull a, ull b) {
    ull d; asm("add.rn.f32x2 %0, %1, %2;" : "=l"(d) : "l"(a), "l"(b)); return d;
}
__device__ __forceinline__ ull pk(float lo, float hi) {
    ull r; asm("mov.b64 %0, {%1, %2};" : "=l"(r) : "f"(lo), "f"(hi)); return r;
}
__device__ __forceinline__ void upk(ull v, float& lo, float& hi) {
    asm("mov.b64 {%0, %1}, %2;" : "=f"(lo), "=f"(hi) : "l"(v));
}
__device__ __forceinline__ ull lswap(ull v) {
    float lo, hi; upk(v, lo, hi); return pk(hi, lo);
}

__device__ __forceinline__ int swz4(int j) { return j ^ ((j >> 4) & 15); }

// 7-coeff SU(2) packed butterfly; coefficients via LDS.128 pairs.
template<int NB, int J>
__device__ __forceinline__ void gateP7(ull* re, ull* im, const float* gf) {
    const ulonglong2* g2 = (const ulonglong2*)gf;
    ulonglong2 v01 = g2[0], v23 = g2[1], v45 = g2[2];
    ull X = v01.x, Y = v01.y, nY = v23.x, Z = v23.y, nZ = v45.x, W = v45.y;
    ull nW = ((const ull*)gf)[6];
#pragma unroll
    for (int k = 0; k < (1 << NB); ++k)
        if (!(k & (1 << J))) {
            const int m = k | (1 << J);
            ull p0r = re[k], p0i = im[k], p1r = re[m], p1i = im[m];
            ull n0r = f2fma(nW, p1i, f2fma(Z, p1r, f2fma(nY, p0i, f2mul(X, p0r))));
            ull n0i = f2fma(W,  p1r, f2fma(Z, p1i, f2fma(Y,  p0r, f2mul(X, p0i))));
            ull n1r = f2fma(Y,  p1i, f2fma(X, p1r, f2fma(nW, p0i, f2mul(nZ, p0r))));
            ull n1i = f2fma(nY, p1r, f2fma(X, p1i, f2fma(W,  p0r, f2mul(nZ, p0i))));
            re[k] = n0r; im[k] = n0i; re[m] = n1r; im[m] = n1i;
        }
}

template<int J0,int J1,int J2,int J3>
__device__ __forceinline__ void load16(ull* re, ull* im,
                                       const ull* reP, const ull* imP, int pjb) {
#pragma unroll
    for (int k = 0; k < 16; ++k) {
        int joff = ((k&1)?(1<<J0):0) | ((k&2)?(1<<J1):0)
                 | ((k&4)?(1<<J2):0) | ((k&8)?(1<<J3):0);
        int a = pjb ^ (joff ^ ((joff >> 4) & 15));
        re[k] = reP[a]; im[k] = imP[a];
    }
}

// store with CNOT-chain permutation folded: reg r lands at cube index
// D(r) = (r3, r2^r3, r1^r2^r3, r0^r1^r2^r3)  [= sigma32.sigma21.sigma10 fold]
template<int J0,int J1,int J2,int J3>
__device__ __forceinline__ void store16perm(const ull* re, const ull* im,
                                            ull* reP, ull* imP, int pjb) {
#pragma unroll
    for (int r = 0; r < 16; ++r) {
        const int r0 = r & 1, r1 = (r >> 1) & 1, r2 = (r >> 2) & 1, r3 = (r >> 3) & 1;
        const int d0 = r0 ^ r1 ^ r2 ^ r3, d1 = r1 ^ r2 ^ r3, d2 = r2 ^ r3, d3 = r3;
        int joff = (d0?(1<<J0):0) | (d1?(1<<J1):0) | (d2?(1<<J2):0) | (d3?(1<<J3):0);
        int a = pjb ^ (joff ^ ((joff >> 4) & 15));
        reP[a] = re[r]; imP[a] = im[r];
    }
}

__device__ __forceinline__ float2 cmulf(float2 a, float2 b) {
    return make_float2(a.x*b.x - a.y*b.y, a.x*b.y + a.y*b.x);
}

// wire-13 (amp0 lane) butterfly
__device__ __forceinline__ void gateLaneAll(ull* re, ull* im, const float* gf) {
    const ulonglong2* g2 = (const ulonglong2*)gf;
    ulonglong2 v01 = g2[0], v23 = g2[1], v45 = g2[2];
    ull C1 = v01.x, C2 = v01.y, nC2 = v23.x, C3 = v23.y, C4 = v45.x, nC4 = v45.y;
#pragma unroll
    for (int k = 0; k < 16; ++k) {
        ull qr = lswap(re[k]), qi = lswap(im[k]);
        ull nr = f2fma(C4,  qi, f2fma(C3, qr, f2fma(C2,  im[k], f2mul(C1, re[k]))));
        ull ni = f2fma(nC4, qr, f2fma(C3, qi, f2fma(nC2, re[k], f2mul(C1, im[k]))));
        re[k] = nr; im[k] = ni;
    }
}

__device__ __forceinline__ void carriedSwap(ull* re, ull* im) {
#pragma unroll
    for (int k1 = 0; k1 < 8; ++k1) {
        float alo, ahi, blo, bhi;
        upk(re[k1], alo, ahi); upk(re[k1|8], blo, bhi);
        re[k1] = pk(alo, bhi); re[k1|8] = pk(blo, ahi);
        upk(im[k1], alo, ahi); upk(im[k1|8], blo, bhi);
        im[k1] = pk(alo, bhi); im[k1|8] = pk(blo, ahi);
    }
}

__device__ __forceinline__ void gateShfl(ull* re, ull* im, const float* gf) {
    const ulonglong2* g2 = (const ulonglong2*)gf;
    ulonglong2 v01 = g2[0], v23 = g2[1], v45 = g2[2];
    ull Ax = v01.x, Ay = v01.y, nAy = v23.x, Az = v23.y, Aw = v45.x, nAw = v45.y;
#pragma unroll
    for (int k = 0; k < 16; ++k) {
        ull qr = __shfl_xor_sync(0xffffffffu, re[k], 1);
        ull qi = __shfl_xor_sync(0xffffffffu, im[k], 1);
        ull nr = f2fma(nAw, qi, f2fma(Az, qr, f2fma(nAy, im[k], f2mul(Ax, re[k]))));
        ull ni = f2fma(Aw,  qr, f2fma(Az, qi, f2fma(Ay,  re[k], f2mul(Ax, im[k]))));
        re[k] = nr; im[k] = ni;
    }
}

__device__ __forceinline__ void pass_a(ull* reP, ull* imP, const float* gl,
                                       int tid, bool carry) {
    int pjb = swz4(tid);
    ull re[16], im[16];
    load16<9,10,11,12>(re, im, reP, imP, pjb);
    if (carry) carriedSwap(re, im);
    gateP7<4,3>(re, im, gl + 0*16);
    gateP7<4,2>(re, im, gl + 1*16);
    gateP7<4,1>(re, im, gl + 2*16);
    gateP7<4,0>(re, im, gl + 3*16);
    gateLaneAll(re, im, gl + 13*16);
    store16perm<9,10,11,12>(re, im, reP, imP, pjb);   // CNOT(0,1)(1,2)(2,3) folded
}
__device__ __forceinline__ void pass_b(ull* reP, ull* imP, const float* gl, int tid) {
    int base = (tid & 31) | ((tid >> 5) << 9);
    int pjb = swz4(base);
    ull re[16], im[16];
    load16<5,6,7,8>(re, im, reP, imP, pjb);
    gateP7<4,3>(re, im, gl + 4*16);
    gateP7<4,2>(re, im, gl + 5*16);
    gateP7<4,1>(re, im, gl + 6*16);
    gateP7<4,0>(re, im, gl + 7*16);
    // CNOT(3,4)[pred tid5] + chain folded: pred toggles all 4 cube bits through
    // the cascade -> pjb ^= swzmap(joff(15)) = 0x1EE
    int pjb2 = pjb ^ (((tid >> 5) & 1) ? 0x1EE : 0);
    store16perm<5,6,7,8>(re, im, reP, imP, pjb2);
}
__device__ __forceinline__ void pass_c(ull* reP, ull* imP, const float* gl,
                                       const float* g8, int tid) {
    int pjb = swz4(tid << 4);
    ull re[16], im[16];
    load16<0,1,2,3>(re, im, reP, imP, pjb);
    gateShfl(re, im, g8 + (tid & 3) * 12);
    gateP7<4,3>(re, im, gl + 9*16);
    gateP7<4,2>(re, im, gl + 10*16);
    gateP7<4,1>(re, im, gl + 11*16);
    gateP7<4,0>(re, im, gl + 12*16);
    const int p = tid & 1;       // CNOT(8,9) ctrl amp5
    // CNOT(12,13): lane-swap regs whose FINAL cube pos has bit0=1:
    // bit0(final(r)) = parity(r) ^ p
#pragma unroll
    for (int r = 0; r < 16; ++r) {
        const int par = (__popc(r) & 1);
        if (par != p) { re[r] = lswap(re[r]); im[r] = lswap(im[r]); }
    }
    // cswap(bit3,pred p) + chain folded: pjb ^= swzmap(joff(15)) = 0xF
    int pjb2 = pjb ^ (p ? 0xF : 0);
    store16perm<0,1,2,3>(re, im, reP, imP, pjb2);
    // CNOT(13,0) carried to next layer's pass A
}

__global__ void __launch_bounds__(NT, 1)
vqc_kernel(const float* __restrict__ x,    const float* __restrict__ w_in,
           const float* __restrict__ b_in, const float* __restrict__ wts,
           const float* __restrict__ w_out,const float* __restrict__ b_out,
           float* __restrict__ out)
{
    extern __shared__ float smem[];
    float* reF   = smem;
    float* imF   = smem + DIM;
    float* gmat  = smem + 2 * DIM;          // 42*16 = 672
    float* g8tab = gmat + 42 * 16;          // 144
    float* enc   = g8tab + 144;             // 28
    float* red   = enc + 28;                // 240
    ull* reP = (ull*)reF;
    ull* imP = (ull*)imF;
    float2* ftab = (float2*)red;            // init factor table (56 floats)

    const int b = blockIdx.x, tid = threadIdx.x;

    if (tid < NQ) {
        float acc = b_in[tid];
#pragma unroll
        for (int s2 = 0; s2 < SEQL; ++s2) acc += x[b*SEQL + s2] * w_in[tid*SEQL + s2];
        enc[2*tid]     = cospif(0.5f * acc);
        enc[2*tid + 1] = sinpif(0.5f * acc);
    }
    __syncthreads();

    if (tid < NQ * NL) {
        int i = tid % NQ, j = tid / NQ;
        const float* w = wts + (i*NL + j)*3;
        float cx = cosf(0.5f*w[0]), sx = sinf(0.5f*w[0]);
        float cy = cosf(0.5f*w[1]), sy = sinf(0.5f*w[1]);
        float cz = cosf(0.5f*w[2]), sz = sinf(0.5f*w[2]);
        if (j == 3) { cz = 1.f; sz = 0.f; }
        float2 m00 = make_float2( cy*cx,  sy*sx);
        float2 m01 = make_float2(-sy*cx, -cy*sx);
        float2 e0 = make_float2(cz, -sz);
        float2 u00 = cmulf(e0, m00), u01 = cmulf(e0, m01);
        float X = u00.x, Y = u00.y, Z = u01.x, W = u01.y;
        float2 u10 = make_float2(-Z, W);   // -conj(u01)
        float2 u11 = make_float2(X, -Y);   //  conj(u00)
        if (j == 0) {
            float c = enc[2*i], s = enc[2*i+1];
            int t = 13 - i;
            ftab[t*2 + 0] = make_float2(X*c + Z*s,         Y*c + W*s);
            ftab[t*2 + 1] = make_float2(u10.x*c + u11.x*s, u10.y*c + u11.y*s);
        } else if (i == 8) {
            float2 Ca[4] = { u00, u11, u10, u01 };
            float2 Cb[4] = { u01, u10, u11, u00 };
#pragma unroll
            for (int s4 = 0; s4 < 4; ++s4) {
                float* r = g8tab + ((j-1)*4 + s4)*12;
                r[0]=Ca[s4].x; r[1]=Ca[s4].x;  r[2]=Ca[s4].y; r[3]=Ca[s4].y;
                r[4]=-Ca[s4].y; r[5]=-Ca[s4].y; r[6]=Cb[s4].x; r[7]=Cb[s4].x;
                r[8]=Cb[s4].y; r[9]=Cb[s4].y;  r[10]=-Cb[s4].y; r[11]=-Cb[s4].y;
            }
        } else {
            float* g = gmat + ((j-1)*NQ + i)*16;
            if (i < 13) {
                g[0]=X;  g[1]=X;   g[2]=Y;  g[3]=Y;   g[4]=-Y; g[5]=-Y;
                g[6]=Z;  g[7]=Z;   g[8]=-Z; g[9]=-Z;  g[10]=W; g[11]=W;
                g[12]=-W; g[13]=-W; g[14]=0.f; g[15]=0.f;
            } else {
                g[0]=X;  g[1]=X;   g[2]=-Y; g[3]=Y;   g[4]=Y;  g[5]=-Y;
                g[6]=Z;  g[7]=-Z;  g[8]=-W; g[9]=-W;  g[10]=W; g[11]=W;
                g[12]=0.f; g[13]=0.f; g[14]=0.f; g[15]=0.f;
            }
        }
    }
    __syncthreads();

    // --- layer 2 pass A fused with init (amps synthesized in registers) ---
    {
        const float* gl = gmat;
        int gx = tid ^ (tid >> 1);
        float2 P8 = ftab[2 + (gx & 1)];
#pragma unroll
        for (int t = 2; t <= 8; ++t)
            P8 = cmulf(P8, ftab[t*2 + ((gx >> (t-1)) & 1)]);
        float2 Bl0 = cmulf(P8, ftab[0 + (tid & 1)]);
        float2 Bl1 = cmulf(P8, ftab[0 + ((tid & 1) ^ 1)]);
        float2 G00 = cmulf(ftab[24], ftab[26]);
        float2 G01 = cmulf(ftab[24], ftab[27]);
        float2 G10 = cmulf(ftab[25], ftab[26]);
        float2 G11 = cmulf(ftab[25], ftab[27]);
        int t8 = (tid >> 8) & 1;
        ull re[16], im[16];
#pragma unroll
        for (int k = 0; k < 16; ++k) {
            const int k0 = k & 1, k1 = (k >> 1) & 1, k2 = (k >> 2) & 1, k3 = (k >> 3) & 1;
            float2 H3 = cmulf(cmulf(ftab[18 + (t8 ^ k0)], ftab[20 + (k0 ^ k1)]),
                              ftab[22 + (k1 ^ k2)]);
            const int a0 = k2 ^ k3, b0c = k3;
            float2 HL0 = cmulf(H3, a0 ? (b0c ? G11 : G10) : (b0c ? G01 : G00));
            float2 HL1 = cmulf(H3, (a0^1) ? ((b0c^1) ? G11 : G10) : ((b0c^1) ? G01 : G00));
            float2 lo = cmulf(Bl0, HL0);
            float2 hi = cmulf(Bl1, HL1);
            re[k] = pk(lo.x, hi.x);
            im[k] = pk(lo.y, hi.y);
        }
        gateP7<4,3>(re, im, gl + 0*16);
        gateP7<4,2>(re, im, gl + 1*16);
        gateP7<4,1>(re, im, gl + 2*16);
        gateP7<4,0>(re, im, gl + 3*16);
        gateLaneAll(re, im, gl + 13*16);
        store16perm<9,10,11,12>(re, im, reP, imP, swz4(tid));
    }
    __syncthreads();
    pass_b(reP, imP, gmat, tid);              __syncthreads();
    pass_c(reP, imP, gmat, g8tab, tid);       __syncthreads();

    // --- layer 3 ---
    pass_a(reP, imP, gmat + NQ*16, tid, true);      __syncthreads();
    pass_b(reP, imP, gmat + NQ*16, tid);            __syncthreads();
    pass_c(reP, imP, gmat + NQ*16, g8tab + 48, tid);__syncthreads();

    // --- layer 4: A(carry), B, then C fused with readout ---
    {
        const float* gl = gmat + 2 * NQ * 16;
        const float* g8 = g8tab + 2 * 48;
        pass_a(reP, imP, gl, tid, true);  __syncthreads();
        pass_b(reP, imP, gl, tid);        __syncthreads();

        int pjb = swz4(tid << 4);
        ull re[16], im[16];
        load16<0,1,2,3>(re, im, reP, imP, pjb);
        gateShfl(re, im, g8 + (tid & 1) * 12);
        gateP7<4,3>(re, im, gl + 9*16);
        gateP7<4,2>(re, im, gl + 10*16);
        gateP7<4,1>(re, im, gl + 11*16);
        gateP7<4,0>(re, im, gl + 12*16);

        ull accP = 0, acc9 = 0, acc10 = 0, acc11 = 0, acc12 = 0;
        const ull NEG1 = 0xBF800000BF800000ull;
#pragma unroll
        for (int k = 0; k < 16; ++k) {
            ull p = f2fma(im[k], im[k], f2mul(re[k], re[k]));
            accP = f2add(accP, p);
            int k3 = (k >> 3) & 1;
            int k23 = ((k >> 2) ^ (k >> 3)) & 1;
            int k123 = ((k >> 1) ^ (k >> 2) ^ (k >> 3)) & 1;
            int kpar = __popc(k) & 1;
            acc9  = k3   ? f2fma(p, NEG1, acc9)  : f2add(acc9,  p);
            acc10 = k23  ? f2fma(p, NEG1, acc10) : f2add(acc10, p);
            acc11 = k123 ? f2fma(p, NEG1, acc11) : f2add(acc11, p);
            acc12 = kpar ? f2fma(p, NEG1, acc12) : f2add(acc12, p);
        }
        float z[NQ];
        {
            float Pl, Ph;  upk(accP, Pl, Ph);   float Ps = Pl + Ph;
            float l9, h9;  upk(acc9, l9, h9);
            float l10,h10; upk(acc10,l10,h10);
            float l11,h11; upk(acc11,l11,h11);
            float l12,h12; upk(acc12,l12,h12);
            int t01 = (tid ^ (tid >> 1)) & 1;
            float f5 = t01 ? -1.f : 1.f;
            z[1] = (tid & 128) ? -Ps : Ps;
            z[2] = (tid & 64)  ? -Ps : Ps;
            z[3] = (tid & 32)  ? -Ps : Ps;
            z[4] = (tid & 16)  ? -Ps : Ps;
            z[5] = (tid & 8)   ? -Ps : Ps;
            z[6] = (tid & 4)   ? -Ps : Ps;
            z[7] = (tid & 2)   ? -Ps : Ps;
            z[8] = t01 ? -Ps : Ps;
            z[9]  = f5 * (l9  + h9);
            z[10] = f5 * (l10 + h10);
            z[11] = f5 * (l11 + h11);
            z[12] = f5 * (l12 + h12);
            z[13] = f5 * (l12 - h12);
            z[0]  = (tid & 256) ? -z[13] : z[13];
        }

#pragma unroll
        for (int w = 0; w < NQ; ++w)
#pragma unroll
            for (int o = 16; o; o >>= 1)
                z[w] += __shfl_xor_sync(0xffffffffu, z[w], o);

        __syncthreads();
        if ((tid & 31) == 0) {
            int wr = tid >> 5;
#pragma unroll
            for (int w = 0; w < NQ; ++w) red[wr*NQ + w] = z[w];
        }
        __syncthreads();
        if (tid < NQ) {
            float s = 0.f;
#pragma unroll
            for (int wr = 0; wr < NT/32; ++wr) s += red[wr*NQ + tid];
            red[224 + tid] = s * w_out[tid];
        }
        __syncthreads();
        if (tid == 0) {
            float o = b_out[0];
#pragma unroll
            for (int w = 0; w < NQ; ++w) o += red[224 + w];
            out[b] = o;
        }
    }
}

extern "C" void kernel_launch(void* const* d_in, const int* in_sizes, int n_in,
                              void* d_out, int out_size)
{
    const float* x     = (const float*)d_in[0];
    const float* w_in  = (const float*)d_in[1];
    const float* b_in  = (const float*)d_in[2];
    const float* wts   = (const float*)d_in[3];
    const float* w_out = (const float*)d_in[4];
    const float* b_out = (const float*)d_in[5];
    float* out = (float*)d_out;

    const int B = in_sizes[0] / SEQL;
    const int smem = (2*DIM + 42*16 + 144 + 28 + 240) * (int)sizeof(float);

    cudaFuncSetAttribute(vqc_kernel, cudaFuncAttributeMaxDynamicSharedMemorySize, smem);
    vqc_kernel<<<B, NT, smem>>>(x, w_in, b_in, wts, w_out, b_out, out);
}

// round 17
// speedup vs baseline: 1.1072x; 1.0237x over previous
#include <cuda_runtime.h>
#include <cstdint>

#define NQ   14
#define NL   4
#define DIM  16384
#define NT   512
#define SEQL 8

typedef unsigned long long ull;

// batch-invariant precomputed tables (scratch via __device__ globals — no alloc)
__device__ float g_tab[816];   // [0..671]=gmat (42 slots x16), [672..815]=g8tab
__device__ float g_u0[56];     // layer-0 SU(2) rows: per wire {X,Y,Z,W}

__device__ __forceinline__ ull f2mul(ull a, ull b) {
    ull d; asm("mul.rn.f32x2 %0, %1, %2;" : "=l"(d) : "l"(a), "l"(b)); return d;
}
__device__ __forceinline__ ull f2fma(ull a, ull b, ull c) {
    ull d; asm("fma.rn.f32x2 %0, %1, %2, %3;" : "=l"(d) : "l"(a), "l"(b), "l"(c)); return d;
}
__device__ __forceinline__ ull f2add(ull a, ull b) {
    ull d; asm("add.rn.f32x2 %0, %1, %2;" : "=l"(d) : "l"(a), "l"(b)); return d;
}
__device__ __forceinline__ ull pk(float lo, float hi) {
    ull r; asm("mov.b64 %0, {%1, %2};" : "=l"(r) : "f"(lo), "f"(hi)); return r;
}
__device__ __forceinline__ void upk(ull v, float& lo, float& hi) {
    asm("mov.b64 {%0, %1}, %2;" : "=f"(lo), "=f"(hi) : "l"(v));
}
__device__ __forceinline__ ull lswap(ull v) {
    float lo, hi; upk(v, lo, hi); return pk(hi, lo);
}

__device__ __forceinline__ int swz4(int j) { return j ^ ((j >> 4) & 15); }

__device__ __forceinline__ float2 cmulf(float2 a, float2 b) {
    return make_float2(a.x*b.x - a.y*b.y, a.x*b.y + a.y*b.x);
}

// ---------------------------------------------------------------------------
// Kernel A: one CTA computes all batch-invariant gate tables.
// ---------------------------------------------------------------------------
__global__ void setup_kernel(const float* __restrict__ wts) {
    int tid = threadIdx.x;
    if (tid >= NQ * NL) return;
    int i = tid % NQ, j = tid / NQ;
    const float* w = wts + (i*NL + j)*3;
    float cx = cosf(0.5f*w[0]), sx = sinf(0.5f*w[0]);
    float cy = cosf(0.5f*w[1]), sy = sinf(0.5f*w[1]);
    float cz = cosf(0.5f*w[2]), sz = sinf(0.5f*w[2]);
    if (j == 3) { cz = 1.f; sz = 0.f; }           // final-layer RZ phase-only
    float2 m00 = make_float2( cy*cx,  sy*sx);
    float2 m01 = make_float2(-sy*cx, -cy*sx);
    float2 e0 = make_float2(cz, -sz);
    float2 u00 = cmulf(e0, m00), u01 = cmulf(e0, m01);
    float X = u00.x, Y = u00.y, Z = u01.x, W = u01.y;
    float2 u10 = make_float2(-Z, W);              // -conj(u01)
    float2 u11 = make_float2(X, -Y);              //  conj(u00)
    if (j == 0) {
        float* u = g_u0 + i*4;
        u[0] = X; u[1] = Y; u[2] = Z; u[3] = W;
    } else if (i == 8) {
        float2 Ca[4] = { u00, u11, u10, u01 };
        float2 Cb[4] = { u01, u10, u11, u00 };
#pragma unroll
        for (int s4 = 0; s4 < 4; ++s4) {
            float* r = g_tab + 672 + ((j-1)*4 + s4)*12;
            r[0]=Ca[s4].x; r[1]=Ca[s4].x;  r[2]=Ca[s4].y; r[3]=Ca[s4].y;
            r[4]=-Ca[s4].y; r[5]=-Ca[s4].y; r[6]=Cb[s4].x; r[7]=Cb[s4].x;
            r[8]=Cb[s4].y; r[9]=Cb[s4].y;  r[10]=-Cb[s4].y; r[11]=-Cb[s4].y;
        }
    } else {
        float* g = g_tab + ((j-1)*NQ + i)*16;
        if (i < 13) {   // 7-coeff SU(2): X Y -Y Z -Z W -W (dup pairs)
            g[0]=X;  g[1]=X;   g[2]=Y;  g[3]=Y;   g[4]=-Y; g[5]=-Y;
            g[6]=Z;  g[7]=Z;   g[8]=-Z; g[9]=-Z;  g[10]=W; g[11]=W;
            g[12]=-W; g[13]=-W; g[14]=0.f; g[15]=0.f;
        } else {        // wire 13 lane-distinct: C1 C2 nC2 C3 C4 nC4
            g[0]=X;  g[1]=X;   g[2]=-Y; g[3]=Y;   g[4]=Y;  g[5]=-Y;
            g[6]=Z;  g[7]=-Z;  g[8]=-W; g[9]=-W;  g[10]=W; g[11]=W;
            g[12]=0.f; g[13]=0.f; g[14]=0.f; g[15]=0.f;
        }
    }
}

// ---------------------------------------------------------------------------
// Gate primitives (byte-identical to R16)
// ---------------------------------------------------------------------------
template<int NB, int J>
__device__ __forceinline__ void gateP7(ull* re, ull* im, const float* gf) {
    const ulonglong2* g2 = (const ulonglong2*)gf;
    ulonglong2 v01 = g2[0], v23 = g2[1], v45 = g2[2];
    ull X = v01.x, Y = v01.y, nY = v23.x, Z = v23.y, nZ = v45.x, W = v45.y;
    ull nW = ((const ull*)gf)[6];
#pragma unroll
    for (int k = 0; k < (1 << NB); ++k)
        if (!(k & (1 << J))) {
            const int m = k | (1 << J);
            ull p0r = re[k], p0i = im[k], p1r = re[m], p1i = im[m];
            ull n0r = f2fma(nW, p1i, f2fma(Z, p1r, f2fma(nY, p0i, f2mul(X, p0r))));
            ull n0i = f2fma(W,  p1r, f2fma(Z, p1i, f2fma(Y,  p0r, f2mul(X, p0i))));
            ull n1r = f2fma(Y,  p1i, f2fma(X, p1r, f2fma(nW, p0i, f2mul(nZ, p0r))));
            ull n1i = f2fma(nY, p1r, f2fma(X, p1i, f2fma(W,  p0r, f2mul(nZ, p0i))));
            re[k] = n0r; im[k] = n0i; re[m] = n1r; im[m] = n1i;
        }
}

template<int J0,int J1,int J2,int J3>
__device__ __forceinline__ void load16(ull* re, ull* im,
                                       const ull* reP, const ull* imP, int pjb) {
#pragma unroll
    for (int k = 0; k < 16; ++k) {
        int joff = ((k&1)?(1<<J0):0) | ((k&2)?(1<<J1):0)
                 | ((k&4)?(1<<J2):0) | ((k&8)?(1<<J3):0);
        int a = pjb ^ (joff ^ ((joff >> 4) & 15));
        re[k] = reP[a]; im[k] = imP[a];
    }
}

// store with CNOT-chain permutation folded: reg r lands at cube index
// D(r) = (r3, r2^r3, r1^r2^r3, r0^r1^r2^r3)
template<int J0,int J1,int J2,int J3>
__device__ __forceinline__ void store16perm(const ull* re, const ull* im,
                                            ull* reP, ull* imP, int pjb) {
#pragma unroll
    for (int r = 0; r < 16; ++r) {
        const int r0 = r & 1, r1 = (r >> 1) & 1, r2 = (r >> 2) & 1, r3 = (r >> 3) & 1;
        const int d0 = r0 ^ r1 ^ r2 ^ r3, d1 = r1 ^ r2 ^ r3, d2 = r2 ^ r3, d3 = r3;
        int joff = (d0?(1<<J0):0) | (d1?(1<<J1):0) | (d2?(1<<J2):0) | (d3?(1<<J3):0);
        int a = pjb ^ (joff ^ ((joff >> 4) & 15));
        reP[a] = re[r]; imP[a] = im[r];
    }
}

__device__ __forceinline__ void gateLaneAll(ull* re, ull* im, const float* gf) {
    const ulonglong2* g2 = (const ulonglong2*)gf;
    ulonglong2 v01 = g2[0], v23 = g2[1], v45 = g2[2];
    ull C1 = v01.x, C2 = v01.y, nC2 = v23.x, C3 = v23.y, C4 = v45.x, nC4 = v45.y;
#pragma unroll
    for (int k = 0; k < 16; ++k) {
        ull qr = lswap(re[k]), qi = lswap(im[k]);
        ull nr = f2fma(C4,  qi, f2fma(C3, qr, f2fma(C2,  im[k], f2mul(C1, re[k]))));
        ull ni = f2fma(nC4, qr, f2fma(C3, qi, f2fma(nC2, re[k], f2mul(C1, im[k]))));
        re[k] = nr; im[k] = ni;
    }
}

__device__ __forceinline__ void carriedSwap(ull* re, ull* im) {
#pragma unroll
    for (int k1 = 0; k1 < 8; ++k1) {
        float alo, ahi, blo, bhi;
        upk(re[k1], alo, ahi); upk(re[k1|8], blo, bhi);
        re[k1] = pk(alo, bhi); re[k1|8] = pk(blo, ahi);
        upk(im[k1], alo, ahi); upk(im[k1|8], blo, bhi);
        im[k1] = pk(alo, bhi); im[k1|8] = pk(blo, ahi);
    }
}

__device__ __forceinline__ void gateShfl(ull* re, ull* im, const float* gf) {
    const ulonglong2* g2 = (const ulonglong2*)gf;
    ulonglong2 v01 = g2[0], v23 = g2[1], v45 = g2[2];
    ull Ax = v01.x, Ay = v01.y, nAy = v23.x, Az = v23.y, Aw = v45.x, nAw = v45.y;
#pragma unroll
    for (int k = 0; k < 16; ++k) {
        ull qr = __shfl_xor_sync(0xffffffffu, re[k], 1);
        ull qi = __shfl_xor_sync(0xffffffffu, im[k], 1);
        ull nr = f2fma(nAw, qi, f2fma(Az, qr, f2fma(nAy, im[k], f2mul(Ax, re[k]))));
        ull ni = f2fma(Aw,  qr, f2fma(Az, qi, f2fma(Ay,  re[k], f2mul(Ax, im[k]))));
        re[k] = nr; im[k] = ni;
    }
}

__device__ __forceinline__ void pass_a(ull* reP, ull* imP, const float* gl,
                                       int tid, bool carry) {
    int pjb = swz4(tid);
    ull re[16], im[16];
    load16<9,10,11,12>(re, im, reP, imP, pjb);
    if (carry) carriedSwap(re, im);
    gateP7<4,3>(re, im, gl + 0*16);
    gateP7<4,2>(re, im, gl + 1*16);
    gateP7<4,1>(re, im, gl + 2*16);
    gateP7<4,0>(re, im, gl + 3*16);
    gateLaneAll(re, im, gl + 13*16);
    store16perm<9,10,11,12>(re, im, reP, imP, pjb);
}
__device__ __forceinline__ void pass_b(ull* reP, ull* imP, const float* gl, int tid) {
    int base = (tid & 31) | ((tid >> 5) << 9);
    int pjb = swz4(base);
    ull re[16], im[16];
    load16<5,6,7,8>(re, im, reP, imP, pjb);
    gateP7<4,3>(re, im, gl + 4*16);
    gateP7<4,2>(re, im, gl + 5*16);
    gateP7<4,1>(re, im, gl + 6*16);
    gateP7<4,0>(re, im, gl + 7*16);
    int pjb2 = pjb ^ (((tid >> 5) & 1) ? 0x1EE : 0);
    store16perm<5,6,7,8>(re, im, reP, imP, pjb2);
}
__device__ __forceinline__ void pass_c(ull* reP, ull* imP, const float* gl,
                                       const float* g8, int tid) {
    int pjb = swz4(tid << 4);
    ull re[16], im[16];
    load16<0,1,2,3>(re, im, reP, imP, pjb);
    gateShfl(re, im, g8 + (tid & 3) * 12);
    gateP7<4,3>(re, im, gl + 9*16);
    gateP7<4,2>(re, im, gl + 10*16);
    gateP7<4,1>(re, im, gl + 11*16);
    gateP7<4,0>(re, im, gl + 12*16);
    const int p = tid & 1;
#pragma unroll
    for (int r = 0; r < 16; ++r) {
        const int par = (__popc(r) & 1);
        if (par != p) { re[r] = lswap(re[r]); im[r] = lswap(im[r]); }
    }
    int pjb2 = pjb ^ (p ? 0xF : 0);
    store16perm<0,1,2,3>(re, im, reP, imP, pjb2);
}

// ---------------------------------------------------------------------------
// Kernel B: main. SMEM: re[16384] | im[16384] | tabs[816] | red[240]
// ---------------------------------------------------------------------------
__global__ void __launch_bounds__(NT, 1)
vqc_kernel(const float* __restrict__ x,    const float* __restrict__ w_in,
           const float* __restrict__ b_in, const float* __restrict__ w_out,
           const float* __restrict__ b_out, float* __restrict__ out)
{
    extern __shared__ float smem[];
    float* reF   = smem;
    float* imF   = smem + DIM;
    float* gmat  = smem + 2 * DIM;          // 672
    float* g8tab = gmat + 672;              // 144 (contiguous with gmat)
    float* red   = g8tab + 144;             // 240
    ull* reP = (ull*)reF;
    ull* imP = (ull*)imF;
    float2* ftab = (float2*)red;            // init factor table (56 floats)

    const int b = blockIdx.x, tid = threadIdx.x;

    // --- setup: copy precomputed tables; compute batch-dependent ftab inline
    if (tid < NQ) {
        float acc = b_in[tid];
#pragma unroll
        for (int s2 = 0; s2 < SEQL; ++s2) acc += x[b*SEQL + s2] * w_in[tid*SEQL + s2];
        float c = cospif(0.5f * acc), s = sinpif(0.5f * acc);
        const float* u = g_u0 + tid*4;
        float X = u[0], Y = u[1], Z = u[2], W = u[3];
        int t = 13 - tid;
        ftab[t*2 + 0] = make_float2(X*c + Z*s,  Y*c + W*s);
        ftab[t*2 + 1] = make_float2(-Z*c + X*s, W*c - Y*s);
    }
#pragma unroll
    for (int idx = tid; idx < 816; idx += NT) gmat[idx] = g_tab[idx];
    __syncthreads();

    // --- layer 2 pass A fused with init (amps synthesized in registers) ---
    {
        const float* gl = gmat;
        int gx = tid ^ (tid >> 1);
        float2 P8 = ftab[2 + (gx & 1)];
#pragma unroll
        for (int t = 2; t <= 8; ++t)
            P8 = cmulf(P8, ftab[t*2 + ((gx >> (t-1)) & 1)]);
        float2 Bl0 = cmulf(P8, ftab[0 + (tid & 1)]);
        float2 Bl1 = cmulf(P8, ftab[0 + ((tid & 1) ^ 1)]);
        float2 G00 = cmulf(ftab[24], ftab[26]);
        float2 G01 = cmulf(ftab[24], ftab[27]);
        float2 G10 = cmulf(ftab[25], ftab[26]);
        float2 G11 = cmulf(ftab[25], ftab[27]);
        int t8 = (tid >> 8) & 1;
        ull re[16], im[16];
#pragma unroll
        for (int k = 0; k < 16; ++k) {
            const int k0 = k & 1, k1 = (k >> 1) & 1, k2 = (k >> 2) & 1, k3 = (k >> 3) & 1;
            float2 H3 = cmulf(cmulf(ftab[18 + (t8 ^ k0)], ftab[20 + (k0 ^ k1)]),
                              ftab[22 + (k1 ^ k2)]);
            const int a0 = k2 ^ k3, b0c = k3;
            float2 HL0 = cmulf(H3, a0 ? (b0c ? G11 : G10) : (b0c ? G01 : G00));
            float2 HL1 = cmulf(H3, (a0^1) ? ((b0c^1) ? G11 : G10) : ((b0c^1) ? G01 : G00));
            float2 lo = cmulf(Bl0, HL0);
            float2 hi = cmulf(Bl1, HL1);
            re[k] = pk(lo.x, hi.x);
            im[k] = pk(lo.y, hi.y);
        }
        gateP7<4,3>(re, im, gl + 0*16);
        gateP7<4,2>(re, im, gl + 1*16);
        gateP7<4,1>(re, im, gl + 2*16);
        gateP7<4,0>(re, im, gl + 3*16);
        gateLaneAll(re, im, gl + 13*16);
        store16perm<9,10,11,12>(re, im, reP, imP, swz4(tid));
    }
    __syncthreads();
    pass_b(reP, imP, gmat, tid);              __syncthreads();
    pass_c(reP, imP, gmat, g8tab, tid);       __syncthreads();

    // --- layer 3 ---
    pass_a(reP, imP, gmat + NQ*16, tid, true);      __syncthreads();
    pass_b(reP, imP, gmat + NQ*16, tid);            __syncthreads();
    pass_c(reP, imP, gmat + NQ*16, g8tab + 48, tid);__syncthreads();

    // --- layer 4: A(carry), B, then C fused with readout ---
    {
        const float* gl = gmat + 2 * NQ * 16;
        const float* g8 = g8tab + 2 * 48;
        pass_a(reP, imP, gl, tid, true);  __syncthreads();
        pass_b(reP, imP, gl, tid);        __syncthreads();

        int pjb = swz4(tid << 4);
        ull re[16], im[16];
        load16<0,1,2,3>(re, im, reP, imP, pjb);
        gateShfl(re, im, g8 + (tid & 1) * 12);
        gateP7<4,3>(re, im, gl + 9*16);
        gateP7<4,2>(re, im, gl + 10*16);
        gateP7<4,1>(re, im, gl + 11*16);
        gateP7<4,0>(re, im, gl + 12*16);

        ull accP = 0, acc9 = 0, acc10 = 0, acc11 = 0, acc12 = 0;
        const ull NEG1 = 0xBF800000BF800000ull;
#pragma unroll
        for (int k = 0; k < 16; ++k) {
            ull p = f2fma(im[k], im[k], f2mul(re[k], re[k]));
            accP = f2add(accP, p);
            int k3 = (k >> 3) & 1;
            int k23 = ((k >> 2) ^ (k >> 3)) & 1;
            int k123 = ((k >> 1) ^ (k >> 2) ^ (k >> 3)) & 1;
            int kpar = __popc(k) & 1;
            acc9  = k3   ? f2fma(p, NEG1, acc9)  : f2add(acc9,  p);
            acc10 = k23  ? f2fma(p, NEG1, acc10) : f2add(acc10, p);
            acc11 = k123 ? f2fma(p, NEG1, acc11) : f2add(acc11, p);
            acc12 = kpar ? f2fma(p, NEG1, acc12) : f2add(acc12, p);
        }
        float z[NQ];
        {
            float Pl, Ph;  upk(accP, Pl, Ph);   float Ps = Pl + Ph;
            float l9, h9;  upk(acc9, l9, h9);
            float l10,h10; upk(acc10,l10,h10);
            float l11,h11; upk(acc11,l11,h11);
            float l12,h12; upk(acc12,l12,h12);
            int t01 = (tid ^ (tid >> 1)) & 1;
            float f5 = t01 ? -1.f : 1.f;
            z[1] = (tid & 128) ? -Ps : Ps;
            z[2] = (tid & 64)  ? -Ps : Ps;
            z[3] = (tid & 32)  ? -Ps : Ps;
            z[4] = (tid & 16)  ? -Ps : Ps;
            z[5] = (tid & 8)   ? -Ps : Ps;
            z[6] = (tid & 4)   ? -Ps : Ps;
            z[7] = (tid & 2)   ? -Ps : Ps;
            z[8] = t01 ? -Ps : Ps;
            z[9]  = f5 * (l9  + h9);
            z[10] = f5 * (l10 + h10);
            z[11] = f5 * (l11 + h11);
            z[12] = f5 * (l12 + h12);
            z[13] = f5 * (l12 - h12);
            z[0]  = (tid & 256) ? -z[13] : z[13];
        }

#pragma unroll
        for (int w = 0; w < NQ; ++w)
#pragma unroll
            for (int o = 16; o; o >>= 1)
                z[w] += __shfl_xor_sync(0xffffffffu, z[w], o);

        __syncthreads();
        if ((tid & 31) == 0) {
            int wr = tid >> 5;
#pragma unroll
            for (int w = 0; w < NQ; ++w) red[wr*NQ + w] = z[w];
        }
        __syncthreads();
        if (tid < NQ) {
            float s = 0.f;
#pragma unroll
            for (int wr = 0; wr < NT/32; ++wr) s += red[wr*NQ + tid];
            red[224 + tid] = s * w_out[tid];
        }
        __syncthreads();
        if (tid == 0) {
            float o = b_out[0];
#pragma unroll
            for (int w = 0; w < NQ; ++w) o += red[224 + w];
            out[b] = o;
        }
    }
}

extern "C" void kernel_launch(void* const* d_in, const int* in_sizes, int n_in,
                              void* d_out, int out_size)
{
    const float* x     = (const float*)d_in[0];
    const float* w_in  = (const float*)d_in[1];
    const float* b_in  = (const float*)d_in[2];
    const float* wts   = (const float*)d_in[3];
    const float* w_out = (const float*)d_in[4];
    const float* b_out = (const float*)d_in[5];
    float* out = (float*)d_out;

    const int B = in_sizes[0] / SEQL;
    const int smem = (2*DIM + 816 + 240) * (int)sizeof(float);

    setup_kernel<<<1, 64>>>(wts);
    cudaFuncSetAttribute(vqc_kernel, cudaFuncAttributeMaxDynamicSharedMemorySize, smem);
    vqc_kernel<<<B, NT, smem>>>(x, w_in, b_in, w_out, b_out, out);
}